// round 2
// baseline (speedup 1.0000x reference)
#include <cuda_runtime.h>
#include <math.h>

// ---------------- problem constants (fixed by setup_inputs) ----------------
#define B_   2
#define NQ   2048
#define NKV  2048
#define CQ   1024
#define CK   768
#define HH   8
#define DD   64
#define II   (HH*DD)          // 512
#define SCALE 0.125f          // 64^-0.5

// ---------------- scratch (device globals: allocation-free) ----------------
__device__ float g_Q [B_*NQ *II];   // (b, i, h*D+d)
__device__ float g_K [B_*NKV*II];
__device__ float g_V [B_*NKV*II];
__device__ float g_AO[B_*NQ *II];   // attention output, (b, i, h*D+d)

// ============================================================================
// SGEMM: C[M,N] = A[M,K] @ Bm[K,N] (+ bias).  BM=BN=128, BK=8, 256 threads,
// 8x8 accumulators per thread. Software prefetch of next K-slab into regs.
// ============================================================================
template<bool BIAS>
__global__ __launch_bounds__(256) void sgemm128(const float* __restrict__ A,
                                                const float* __restrict__ Bm,
                                                const float* __restrict__ bias,
                                                float* __restrict__ C,
                                                int M, int N, int K)
{
    __shared__ float As[8][128];   // A tile, transposed: As[k][m]
    __shared__ float Bs[8][128];   // B tile: Bs[k][n]

    const int t  = threadIdx.x;
    const int bm = blockIdx.y * 128;
    const int bn = blockIdx.x * 128;
    const int tr = t >> 4;        // 0..15  (row group)
    const int tc = t & 15;        // 0..15  (col group)

    const int arow = t >> 1;            // 0..127
    const int acol = (t & 1) * 4;       // 0 or 4
    const int brow = t >> 5;            // 0..7
    const int bcol = (t & 31) * 4;      // 0..124

    const float* Aptr = &A[(size_t)(bm + arow) * K + acol];
    const float* Bptr = &Bm[(size_t)brow * N + bn + bcol];

    float acc[8][8];
    #pragma unroll
    for (int i = 0; i < 8; i++)
        #pragma unroll
        for (int j = 0; j < 8; j++) acc[i][j] = 0.f;

    // prologue: load first slab
    float4 av = *(const float4*)Aptr;
    float4 bv = *(const float4*)Bptr;

    for (int kb = 0; kb < K; kb += 8) {
        As[acol+0][arow] = av.x;
        As[acol+1][arow] = av.y;
        As[acol+2][arow] = av.z;
        As[acol+3][arow] = av.w;
        *(float4*)&Bs[brow][bcol] = bv;
        __syncthreads();

        // prefetch next slab while FFMAs run
        if (kb + 8 < K) {
            av = *(const float4*)(Aptr + kb + 8);
            bv = *(const float4*)(Bptr + (size_t)(kb + 8) * N);
        }

        #pragma unroll
        for (int k = 0; k < 8; k++) {
            float ar[8], br[8];
            *(float4*)&ar[0] = *(float4*)&As[k][tr*8];
            *(float4*)&ar[4] = *(float4*)&As[k][tr*8+4];
            *(float4*)&br[0] = *(float4*)&Bs[k][tc*8];
            *(float4*)&br[4] = *(float4*)&Bs[k][tc*8+4];
            #pragma unroll
            for (int i = 0; i < 8; i++)
                #pragma unroll
                for (int j = 0; j < 8; j++)
                    acc[i][j] += ar[i] * br[j];
        }
        __syncthreads();
    }

    #pragma unroll
    for (int i = 0; i < 8; i++) {
        int row = bm + tr*8 + i;
        #pragma unroll
        for (int j4 = 0; j4 < 2; j4++) {
            int col = bn + tc*8 + j4*4;
            float4 o;
            o.x = acc[i][j4*4+0];
            o.y = acc[i][j4*4+1];
            o.z = acc[i][j4*4+2];
            o.w = acc[i][j4*4+3];
            if (BIAS) {
                o.x += bias[col+0];
                o.y += bias[col+1];
                o.z += bias[col+2];
                o.w += bias[col+3];
            }
            *(float4*)&C[(size_t)row * N + col] = o;
        }
    }
}

// ============================================================================
// Flash attention, fp32, D=64.  Block: 64 queries x full head-dim.
// 256 threads = 16x16; each thread holds 4x4 of S and 4x4 of O.
// Streams KV in 64-row tiles with online softmax.
// ============================================================================
__global__ __launch_bounds__(256) void attn64(const float* __restrict__ Qg,
                                              const float* __restrict__ Kg,
                                              const float* __restrict__ Vg,
                                              float* __restrict__ AO)
{
    extern __shared__ float sm[];
    float* Qs   = sm;             // Qs[d*64 + r]   (pre-scaled by SCALE)
    float* KVs  = Qs  + 64*64;    // K: KVs[d*64 + c] ; V: KVs[c*64 + d]
    float* Ss   = KVs + 64*64;    // Ss[r*65 + c]
    float* m_sh = Ss  + 64*65;    // running row max
    float* l_sh = m_sh + 64;      // running row sum
    float* a_sh = l_sh + 64;      // per-tile rescale factor

    const int t  = threadIdx.x;
    const int tx = t & 15;        // col group (kv / d)
    const int ty = t >> 4;        // row group (query)
    const int bh = blockIdx.y;
    const int b  = bh >> 3;
    const int h  = bh & 7;
    const int q0 = blockIdx.x * 64;

    const int lrow = (t >> 4) * 4;     // base row 0..60
    const int ld4  = (t & 15) * 4;     // inner offset 0..60

    // ---- load Q tile (transposed to d-major, pre-scaled) ----
    #pragma unroll
    for (int j = 0; j < 4; j++) {
        int r = lrow + j;
        float4 v = *(const float4*)&Qg[((size_t)(b*NQ + q0 + r)) * II + h*DD + ld4];
        Qs[(ld4+0)*64 + r] = v.x * SCALE;
        Qs[(ld4+1)*64 + r] = v.y * SCALE;
        Qs[(ld4+2)*64 + r] = v.z * SCALE;
        Qs[(ld4+3)*64 + r] = v.w * SCALE;
    }
    if (t < 64) { m_sh[t] = -3.0e38f; l_sh[t] = 0.f; }

    float o_acc[4][4];
    #pragma unroll
    for (int i = 0; i < 4; i++)
        #pragma unroll
        for (int j = 0; j < 4; j++) o_acc[i][j] = 0.f;

    __syncthreads();

    for (int kv0 = 0; kv0 < NKV; kv0 += 64) {
        // ---- load K tile (d-major) ----
        #pragma unroll
        for (int j = 0; j < 4; j++) {
            int c = lrow + j;
            float4 v = *(const float4*)&Kg[((size_t)(b*NKV + kv0 + c)) * II + h*DD + ld4];
            KVs[(ld4+0)*64 + c] = v.x;
            KVs[(ld4+1)*64 + c] = v.y;
            KVs[(ld4+2)*64 + c] = v.z;
            KVs[(ld4+3)*64 + c] = v.w;
        }
        __syncthreads();

        // ---- S = Q K^T (scaled) ----
        float s[4][4];
        #pragma unroll
        for (int i = 0; i < 4; i++)
            #pragma unroll
            for (int j = 0; j < 4; j++) s[i][j] = 0.f;
        #pragma unroll 8
        for (int d = 0; d < 64; d++) {
            float q[4], k[4];
            *(float4*)q = *(float4*)&Qs [d*64 + ty*4];
            *(float4*)k = *(float4*)&KVs[d*64 + tx*4];
            #pragma unroll
            for (int i = 0; i < 4; i++)
                #pragma unroll
                for (int j = 0; j < 4; j++)
                    s[i][j] += q[i] * k[j];
        }
        #pragma unroll
        for (int i = 0; i < 4; i++)
            #pragma unroll
            for (int j = 0; j < 4; j++)
                Ss[(ty*4+i)*65 + tx*4+j] = s[i][j];
        __syncthreads();

        // ---- online softmax, one lane per row (conflict-free via 65-pad) ----
        if (t < 64) {
            float* row = &Ss[t*65];
            float mo = m_sh[t];
            float mt = mo;
            #pragma unroll 8
            for (int c = 0; c < 64; c++) mt = fmaxf(mt, row[c]);
            float alpha = __expf(mo - mt);
            float sum = 0.f;
            #pragma unroll 8
            for (int c = 0; c < 64; c++) {
                float p = __expf(row[c] - mt);
                row[c] = p;
                sum += p;
            }
            m_sh[t] = mt;
            l_sh[t] = l_sh[t] * alpha + sum;
            a_sh[t] = alpha;
        }
        __syncthreads();

        // ---- rescale accumulators ----
        #pragma unroll
        for (int i = 0; i < 4; i++) {
            float al = a_sh[ty*4 + i];
            #pragma unroll
            for (int j = 0; j < 4; j++) o_acc[i][j] *= al;
        }

        // ---- load V tile (c-major, natural) over KVs ----
        #pragma unroll
        for (int j = 0; j < 4; j++) {
            int c = lrow + j;
            float4 v = *(const float4*)&Vg[((size_t)(b*NKV + kv0 + c)) * II + h*DD + ld4];
            *(float4*)&KVs[c*64 + ld4] = v;
        }
        __syncthreads();

        // ---- O += P @ V ----
        #pragma unroll 8
        for (int c = 0; c < 64; c++) {
            float p[4], v[4];
            p[0] = Ss[(ty*4+0)*65 + c];
            p[1] = Ss[(ty*4+1)*65 + c];
            p[2] = Ss[(ty*4+2)*65 + c];
            p[3] = Ss[(ty*4+3)*65 + c];
            *(float4*)v = *(float4*)&KVs[c*64 + tx*4];
            #pragma unroll
            for (int i = 0; i < 4; i++)
                #pragma unroll
                for (int j = 0; j < 4; j++)
                    o_acc[i][j] += p[i] * v[j];
        }
        __syncthreads();   // before next tile overwrites KVs / Ss
    }

    // ---- normalize + store ----
    #pragma unroll
    for (int i = 0; i < 4; i++) {
        int r = ty*4 + i;
        float inv = 1.0f / l_sh[r];
        float4 o;
        o.x = o_acc[i][0] * inv;
        o.y = o_acc[i][1] * inv;
        o.z = o_acc[i][2] * inv;
        o.w = o_acc[i][3] * inv;
        *(float4*)&AO[((size_t)(b*NQ + q0 + r)) * II + h*DD + tx*4] = o;
    }
}

// ============================================================================
// launch
// ============================================================================
extern "C" void kernel_launch(void* const* d_in, const int* in_sizes, int n_in,
                              void* d_out, int out_size)
{
    const float* x   = (const float*)d_in[0];
    const float* ctx = (const float*)d_in[1];
    const float* Wq  = (const float*)d_in[2];
    const float* Wk  = (const float*)d_in[3];
    const float* Wv  = (const float*)d_in[4];
    const float* Wo  = (const float*)d_in[5];
    const float* bo  = (const float*)d_in[6];
    float* out = (float*)d_out;

    float *Qp, *Kp, *Vp, *AOp;
    cudaGetSymbolAddress((void**)&Qp,  g_Q);
    cudaGetSymbolAddress((void**)&Kp,  g_K);
    cudaGetSymbolAddress((void**)&Vp,  g_V);
    cudaGetSymbolAddress((void**)&AOp, g_AO);

    dim3 blk(256);

    // projections
    sgemm128<false><<<dim3(II/128, (B_*NQ )/128), blk>>>(x,   Wq, nullptr, Qp, B_*NQ,  II, CQ);
    sgemm128<false><<<dim3(II/128, (B_*NKV)/128), blk>>>(ctx, Wk, nullptr, Kp, B_*NKV, II, CK);
    sgemm128<false><<<dim3(II/128, (B_*NKV)/128), blk>>>(ctx, Wv, nullptr, Vp, B_*NKV, II, CK);

    // attention
    int smem = (64*64 + 64*64 + 64*65 + 3*64) * (int)sizeof(float);   // 50176 B
    cudaFuncSetAttribute(attn64, cudaFuncAttributeMaxDynamicSharedMemorySize, smem);
    attn64<<<dim3(NQ/64, B_*HH), blk, smem>>>(Qp, Kp, Vp, AOp);

    // output projection + bias
    sgemm128<true><<<dim3(CQ/128, (B_*NQ)/128), blk>>>(AOp, Wo, bo, out, B_*NQ, CQ, II);
}

// round 3
// speedup vs baseline: 1.0089x; 1.0089x over previous
#include <cuda_runtime.h>
#include <math.h>

// ---------------- problem constants ----------------
#define B_   2
#define NQ   2048
#define NKV  2048
#define CQ   1024
#define CK   768
#define HH   8
#define DD   64
#define II   (HH*DD)          // 512
#define SCALE 0.125f

// ---------------- scratch ----------------
__device__ float g_Q [B_*NQ *II];
__device__ float g_K [B_*NKV*II];
__device__ float g_V [B_*NKV*II];
__device__ float g_AO[B_*NQ *II];

// ============================================================================
// SGEMM body: C[M,N] = A@B (+bias). BM=BN=128, BK=8, 256 thr, 8x8 acc,
// 2-stage smem double buffer (one barrier per slab).
// ============================================================================
template<bool BIAS>
__device__ __forceinline__ void sgemm_body(const float* __restrict__ A,
                                           const float* __restrict__ Bm,
                                           const float* __restrict__ bias,
                                           float* __restrict__ C,
                                           int M, int N, int K, int bm, int bn,
                                           float* As, float* Bs)
{
    const int t  = threadIdx.x;
    const int tr = t >> 4;
    const int tc = t & 15;
    const int arow = t >> 1;
    const int acol = (t & 1) * 4;
    const int brow = t >> 5;
    const int bcol = (t & 31) * 4;

    const float* Aptr = A + (size_t)(bm + arow) * K + acol;
    const float* Bptr = Bm + (size_t)brow * N + bn + bcol;

    float4 av = *(const float4*)Aptr;
    float4 bv = *(const float4*)Bptr;

    As[(acol+0)*128 + arow] = av.x;
    As[(acol+1)*128 + arow] = av.y;
    As[(acol+2)*128 + arow] = av.z;
    As[(acol+3)*128 + arow] = av.w;
    *(float4*)&Bs[brow*128 + bcol] = bv;
    __syncthreads();

    float acc[8][8];
    #pragma unroll
    for (int i = 0; i < 8; i++)
        #pragma unroll
        for (int j = 0; j < 8; j++) acc[i][j] = 0.f;

    int stage = 0;
    for (int kb = 0; kb < K; kb += 8) {
        const bool more = (kb + 8) < K;
        if (more) {
            av = *(const float4*)(Aptr + kb + 8);
            bv = *(const float4*)(Bptr + (size_t)(kb + 8) * N);
        }
        const float* Asc = As + stage * 1024;
        const float* Bsc = Bs + stage * 1024;
        #pragma unroll
        for (int k = 0; k < 8; k++) {
            float ar[8], br[8];
            *(float4*)&ar[0] = *(const float4*)&Asc[k*128 + tr*8];
            *(float4*)&ar[4] = *(const float4*)&Asc[k*128 + tr*8 + 4];
            *(float4*)&br[0] = *(const float4*)&Bsc[k*128 + tc*8];
            *(float4*)&br[4] = *(const float4*)&Bsc[k*128 + tc*8 + 4];
            #pragma unroll
            for (int i = 0; i < 8; i++)
                #pragma unroll
                for (int j = 0; j < 8; j++)
                    acc[i][j] += ar[i] * br[j];
        }
        if (more) {
            float* Asn = As + (stage ^ 1) * 1024;
            float* Bsn = Bs + (stage ^ 1) * 1024;
            Asn[(acol+0)*128 + arow] = av.x;
            Asn[(acol+1)*128 + arow] = av.y;
            Asn[(acol+2)*128 + arow] = av.z;
            Asn[(acol+3)*128 + arow] = av.w;
            *(float4*)&Bsn[brow*128 + bcol] = bv;
        }
        __syncthreads();
        stage ^= 1;
    }

    #pragma unroll
    for (int i = 0; i < 8; i++) {
        int row = bm + tr*8 + i;
        #pragma unroll
        for (int j4 = 0; j4 < 2; j4++) {
            int col = bn + tc*8 + j4*4;
            float4 o;
            o.x = acc[i][j4*4+0];
            o.y = acc[i][j4*4+1];
            o.z = acc[i][j4*4+2];
            o.w = acc[i][j4*4+3];
            if (BIAS) {
                o.x += bias[col+0];
                o.y += bias[col+1];
                o.z += bias[col+2];
                o.w += bias[col+3];
            }
            *(float4*)&C[(size_t)row * N + col] = o;
        }
    }
}

template<bool BIAS>
__global__ __launch_bounds__(256) void sgemm(const float* __restrict__ A,
                                             const float* __restrict__ Bm,
                                             const float* __restrict__ bias,
                                             float* __restrict__ C,
                                             int M, int N, int K)
{
    __shared__ float As[2*8*128];
    __shared__ float Bs[2*8*128];
    sgemm_body<BIAS>(A, Bm, bias, C, M, N, K,
                     blockIdx.y*128, blockIdx.x*128, As, Bs);
}

// fused K and V projection: z=0 -> K, z=1 -> V
__global__ __launch_bounds__(256) void sgemm_kv(const float* __restrict__ ctx,
                                                const float* __restrict__ Wk,
                                                const float* __restrict__ Wv,
                                                float* __restrict__ Kp,
                                                float* __restrict__ Vp)
{
    __shared__ float As[2*8*128];
    __shared__ float Bs[2*8*128];
    const float* Bm = blockIdx.z ? Wv : Wk;
    float*       C  = blockIdx.z ? Vp : Kp;
    sgemm_body<false>(ctx, Bm, nullptr, C, B_*NKV, II, CK,
                      blockIdx.y*128, blockIdx.x*128, As, Bs);
}

// ============================================================================
// Flash attention: 64q x 128kv tile per CTA, 256 thr (16x16), per-thread
// 4x8 S-tile, in-register shfl softmax (rows live in 16-lane half-warps),
// P overwrites K's smem buffer. XOR-swizzled d-major Q/K tiles.
// smem: Qs 4096 + KP 8448 + Vs 8192 floats = 82944 B -> 2 CTAs/SM.
// ============================================================================
__global__ __launch_bounds__(256, 2) void attn_fa(const float* __restrict__ Qg,
                                                  const float* __restrict__ Kg,
                                                  const float* __restrict__ Vg,
                                                  float* __restrict__ AO)
{
    extern __shared__ float smx[];
    float* Qs = smx;                 // [64d][64r] swizzled
    float* KP = smx + 4096;          // K: [64d][128c] swizzled ; P: [64r][132c]
    float* Vs = smx + 4096 + 8448;   // [128c][64d]

    const int t  = threadIdx.x;
    const int tx = t & 15;
    const int ty = t >> 4;
    const int bh = blockIdx.y;
    const int b  = bh >> 3;
    const int h  = bh & 7;
    const int q0 = blockIdx.x * 64;

    // ---- load Q (64x64), transpose to d-major, swizzled, pre-scaled ----
    #pragma unroll
    for (int j = 0; j < 4; j++) {
        int s  = t + j*256;
        int r  = s >> 4;
        int c4 = s & 15;
        int d  = c4 * 4;
        float4 v = *(const float4*)&Qg[((size_t)(b*NQ + q0 + r))*II + h*DD + d];
        int rs = r ^ ((c4 & 7) << 3);
        Qs[(d+0)*64 + rs] = v.x * SCALE;
        Qs[(d+1)*64 + rs] = v.y * SCALE;
        Qs[(d+2)*64 + rs] = v.z * SCALE;
        Qs[(d+3)*64 + rs] = v.w * SCALE;
    }

    float o[4][4];
    float m[4], l[4];
    #pragma unroll
    for (int i = 0; i < 4; i++) {
        m[i] = -1e30f; l[i] = 0.f;
        #pragma unroll
        for (int j = 0; j < 4; j++) o[i][j] = 0.f;
    }

    for (int kv0 = 0; kv0 < NKV; kv0 += 128) {
        // ---- load K (d-major swizzled) and V (c-major) ----
        #pragma unroll
        for (int j = 0; j < 8; j++) {
            int s  = t + j*256;
            int c  = s >> 4;
            int c4 = s & 15;
            int d  = c4 * 4;
            size_t grow = ((size_t)(b*NKV + kv0 + c))*II + h*DD + d;
            float4 kv = *(const float4*)&Kg[grow];
            int cs = c ^ ((c4 & 7) << 3);
            KP[(d+0)*128 + cs] = kv.x;
            KP[(d+1)*128 + cs] = kv.y;
            KP[(d+2)*128 + cs] = kv.z;
            KP[(d+3)*128 + cs] = kv.w;
            float4 vv = *(const float4*)&Vg[grow];
            *(float4*)&Vs[c*64 + d] = vv;
        }
        __syncthreads();

        // ---- S = Q K^T : per-thread 4x8 ----
        float sc[4][8];
        #pragma unroll
        for (int i = 0; i < 4; i++)
            #pragma unroll
            for (int j = 0; j < 8; j++) sc[i][j] = 0.f;

        #pragma unroll 8
        for (int d = 0; d < 64; d++) {
            int swz = ((d >> 2) & 7) << 3;
            float q[4], k[8];
            *(float4*)&q[0] = *(const float4*)&Qs[d*64 + ((ty*4) ^ swz)];
            int kbase = d*128 + ((tx*8) ^ swz);
            *(float4*)&k[0] = *(const float4*)&KP[kbase];
            *(float4*)&k[4] = *(const float4*)&KP[kbase + 4];
            #pragma unroll
            for (int i = 0; i < 4; i++)
                #pragma unroll
                for (int j = 0; j < 8; j++)
                    sc[i][j] += q[i] * k[j];
        }

        // ---- online softmax in registers (reduce across 16-lane row group) ----
        float alpha[4];
        #pragma unroll
        for (int i = 0; i < 4; i++) {
            float mt = sc[i][0];
            #pragma unroll
            for (int j = 1; j < 8; j++) mt = fmaxf(mt, sc[i][j]);
            #pragma unroll
            for (int off = 1; off < 16; off <<= 1)
                mt = fmaxf(mt, __shfl_xor_sync(0xffffffffu, mt, off));
            float mn = fmaxf(m[i], mt);
            alpha[i] = __expf(m[i] - mn);
            m[i] = mn;
            float ps = 0.f;
            #pragma unroll
            for (int j = 0; j < 8; j++) {
                float p = __expf(sc[i][j] - mn);
                sc[i][j] = p;
                ps += p;
            }
            #pragma unroll
            for (int off = 1; off < 16; off <<= 1)
                ps += __shfl_xor_sync(0xffffffffu, ps, off);
            l[i] = l[i]*alpha[i] + ps;
        }

        __syncthreads();   // everyone done reading K before P overwrites it

        // ---- store P (row-major, stride 132) ----
        #pragma unroll
        for (int i = 0; i < 4; i++) {
            int base = (ty*4 + i)*132 + tx*8;
            *(float4*)&KP[base]     = make_float4(sc[i][0], sc[i][1], sc[i][2], sc[i][3]);
            *(float4*)&KP[base + 4] = make_float4(sc[i][4], sc[i][5], sc[i][6], sc[i][7]);
        }
        // rescale accumulators
        #pragma unroll
        for (int i = 0; i < 4; i++)
            #pragma unroll
            for (int j = 0; j < 4; j++) o[i][j] *= alpha[i];
        __syncthreads();

        // ---- O += P @ V ----
        #pragma unroll 4
        for (int c4 = 0; c4 < 32; c4++) {
            float pr[4][4];
            #pragma unroll
            for (int i = 0; i < 4; i++)
                *(float4*)&pr[i][0] = *(const float4*)&KP[(ty*4 + i)*132 + c4*4];
            #pragma unroll
            for (int e = 0; e < 4; e++) {
                float vv[4];
                *(float4*)&vv[0] = *(const float4*)&Vs[(c4*4 + e)*64 + tx*4];
                #pragma unroll
                for (int i = 0; i < 4; i++)
                    #pragma unroll
                    for (int j = 0; j < 4; j++)
                        o[i][j] += pr[i][e] * vv[j];
            }
        }
        __syncthreads();   // protect KP/Vs before next tile's loads
    }

    // ---- normalize + store ----
    #pragma unroll
    for (int i = 0; i < 4; i++) {
        float inv = 1.0f / l[i];
        float4 ov;
        ov.x = o[i][0] * inv;
        ov.y = o[i][1] * inv;
        ov.z = o[i][2] * inv;
        ov.w = o[i][3] * inv;
        *(float4*)&AO[((size_t)(b*NQ + q0 + ty*4 + i))*II + h*DD + tx*4] = ov;
    }
}

// ============================================================================
// launch
// ============================================================================
extern "C" void kernel_launch(void* const* d_in, const int* in_sizes, int n_in,
                              void* d_out, int out_size)
{
    const float* x   = (const float*)d_in[0];
    const float* ctx = (const float*)d_in[1];
    const float* Wq  = (const float*)d_in[2];
    const float* Wk  = (const float*)d_in[3];
    const float* Wv  = (const float*)d_in[4];
    const float* Wo  = (const float*)d_in[5];
    const float* bo  = (const float*)d_in[6];
    float* out = (float*)d_out;

    float *Qp, *Kp, *Vp, *AOp;
    cudaGetSymbolAddress((void**)&Qp,  g_Q);
    cudaGetSymbolAddress((void**)&Kp,  g_K);
    cudaGetSymbolAddress((void**)&Vp,  g_V);
    cudaGetSymbolAddress((void**)&AOp, g_AO);

    dim3 blk(256);

    // Q projection: 4096x512x1024
    sgemm<false><<<dim3(II/128, (B_*NQ)/128), blk>>>(x, Wq, nullptr, Qp, B_*NQ, II, CQ);
    // K+V projections fused: 2 x (4096x512x768)
    sgemm_kv<<<dim3(II/128, (B_*NKV)/128, 2), blk>>>(ctx, Wk, Wv, Kp, Vp);

    // attention
    int smem = (4096 + 8448 + 8192) * (int)sizeof(float);   // 82944 B
    cudaFuncSetAttribute(attn_fa, cudaFuncAttributeMaxDynamicSharedMemorySize, smem);
    attn_fa<<<dim3(NQ/64, B_*HH), blk, smem>>>(Qp, Kp, Vp, AOp);

    // output projection + bias: 4096x1024x512
    sgemm<true><<<dim3(CQ/128, (B_*NQ)/128), blk>>>(AOp, Wo, bo, out, B_*NQ, CQ, II);
}

// round 4
// speedup vs baseline: 2.6330x; 2.6097x over previous
#include <cuda_runtime.h>
#include <math.h>
#include <stdint.h>

// ---------------- problem constants ----------------
#define B_   2
#define NQ   2048
#define NKV  2048
#define CQ   1024
#define CK   768
#define HH   8
#define DD   64
#define II   (HH*DD)          // 512
#define SCALE 0.125f

// ---------------- scratch ----------------
__device__ float g_Q [B_*NQ *II];
__device__ float g_K [B_*NKV*II];
__device__ float g_V [B_*NKV*II];
__device__ float g_AO[B_*NQ *II];

// ---------------- tf32 helpers ----------------
__device__ __forceinline__ uint32_t f2tf(float f) {
    uint32_t u;
    asm("cvt.rna.tf32.f32 %0, %1;" : "=r"(u) : "f"(f));
    return u;
}
__device__ __forceinline__ void mma_tf32(float c[4], const uint32_t a[4], const uint32_t b[2]) {
    asm("mma.sync.aligned.m16n8k8.row.col.f32.tf32.tf32.f32 "
        "{%0,%1,%2,%3},{%4,%5,%6,%7},{%8,%9},{%0,%1,%2,%3};"
        : "+f"(c[0]), "+f"(c[1]), "+f"(c[2]), "+f"(c[3])
        : "r"(a[0]), "r"(a[1]), "r"(a[2]), "r"(a[3]), "r"(b[0]), "r"(b[1]));
}

// ============================================================================
// TF32 GEMM: C[M,N] = A[M,K] @ B[K,N] (+bias).
// CTA 128x128, BK=16. 8 warps as 2x4, warp tile 64x32 (4 m-tiles x 4 n-tiles).
// smem strides: A pad 20, B pad 132 (both == 4 mod 32 -> conflict-free frags).
// ============================================================================
#define AS_STRIDE 20
#define BS_STRIDE 132
#define AS_ELEMS (128*AS_STRIDE)   // 2560
#define BS_ELEMS (16*BS_STRIDE)    // 2112

template<bool BIAS>
__device__ __forceinline__ void gemm_tf32_body(const float* __restrict__ A,
                                               const float* __restrict__ Bm,
                                               const float* __restrict__ bias,
                                               float* __restrict__ C,
                                               int M, int N, int K,
                                               int bm, int bn,
                                               uint32_t* As, uint32_t* Bs)
{
    const int t    = threadIdx.x;
    const int lane = t & 31;
    const int w    = t >> 5;
    const int wrow = w >> 2;        // 0..1
    const int wcol = w & 3;         // 0..3
    const int g    = lane >> 2;     // 0..7
    const int tid4 = lane & 3;      // 0..3

    // global load mapping
    const int arow  = t >> 1;           // 0..127
    const int acol0 = (t & 1) * 8;      // 0 or 8
    const int brow  = t >> 4;           // 0..15
    const int bcol0 = (t & 15) * 8;     // 0..120

    const float* Aptr = A + (size_t)(bm + arow) * K + acol0;
    const float* Bptr = Bm + (size_t)brow * N + bn + bcol0;

    float acc[4][4][4];
    #pragma unroll
    for (int mt = 0; mt < 4; mt++)
        #pragma unroll
        for (int nt = 0; nt < 4; nt++)
            #pragma unroll
            for (int e = 0; e < 4; e++) acc[mt][nt][e] = 0.f;

    // prologue: slab 0 -> regs -> smem
    float4 a0 = *(const float4*)(Aptr);
    float4 a1 = *(const float4*)(Aptr + 4);
    float4 b0 = *(const float4*)(Bptr);
    float4 b1 = *(const float4*)(Bptr + 4);
    {
        uint32_t* ap = &As[arow*AS_STRIDE + acol0];
        ap[0]=f2tf(a0.x); ap[1]=f2tf(a0.y); ap[2]=f2tf(a0.z); ap[3]=f2tf(a0.w);
        ap[4]=f2tf(a1.x); ap[5]=f2tf(a1.y); ap[6]=f2tf(a1.z); ap[7]=f2tf(a1.w);
        uint32_t* bp = &Bs[brow*BS_STRIDE + bcol0];
        bp[0]=f2tf(b0.x); bp[1]=f2tf(b0.y); bp[2]=f2tf(b0.z); bp[3]=f2tf(b0.w);
        bp[4]=f2tf(b1.x); bp[5]=f2tf(b1.y); bp[6]=f2tf(b1.z); bp[7]=f2tf(b1.w);
    }
    __syncthreads();

    int stage = 0;
    for (int kb = 0; kb < K; kb += 16) {
        const bool more = (kb + 16) < K;
        if (more) {
            a0 = *(const float4*)(Aptr + kb + 16);
            a1 = *(const float4*)(Aptr + kb + 20);
            b0 = *(const float4*)(Bptr + (size_t)(kb + 16) * N);
            b1 = *(const float4*)(Bptr + (size_t)(kb + 16) * N + 4);
        }

        const uint32_t* Asc = As + stage * AS_ELEMS;
        const uint32_t* Bsc = Bs + stage * BS_ELEMS;

        #pragma unroll
        for (int ks = 0; ks < 2; ks++) {
            uint32_t af[4][4], bf[4][2];
            #pragma unroll
            for (int mt = 0; mt < 4; mt++) {
                int r = (wrow*64 + mt*16 + g) * AS_STRIDE + ks*8 + tid4;
                af[mt][0] = Asc[r];
                af[mt][1] = Asc[r + 8*AS_STRIDE];
                af[mt][2] = Asc[r + 4];
                af[mt][3] = Asc[r + 8*AS_STRIDE + 4];
            }
            #pragma unroll
            for (int nt = 0; nt < 4; nt++) {
                int cidx = wcol*32 + nt*8 + g;
                bf[nt][0] = Bsc[(ks*8 + tid4)*BS_STRIDE + cidx];
                bf[nt][1] = Bsc[(ks*8 + tid4 + 4)*BS_STRIDE + cidx];
            }
            #pragma unroll
            for (int mt = 0; mt < 4; mt++)
                #pragma unroll
                for (int nt = 0; nt < 4; nt++)
                    mma_tf32(acc[mt][nt], af[mt], bf[nt]);
        }

        if (more) {
            uint32_t* Asn = As + (stage ^ 1) * AS_ELEMS;
            uint32_t* Bsn = Bs + (stage ^ 1) * BS_ELEMS;
            uint32_t* ap = &Asn[arow*AS_STRIDE + acol0];
            ap[0]=f2tf(a0.x); ap[1]=f2tf(a0.y); ap[2]=f2tf(a0.z); ap[3]=f2tf(a0.w);
            ap[4]=f2tf(a1.x); ap[5]=f2tf(a1.y); ap[6]=f2tf(a1.z); ap[7]=f2tf(a1.w);
            uint32_t* bp = &Bsn[brow*BS_STRIDE + bcol0];
            bp[0]=f2tf(b0.x); bp[1]=f2tf(b0.y); bp[2]=f2tf(b0.z); bp[3]=f2tf(b0.w);
            bp[4]=f2tf(b1.x); bp[5]=f2tf(b1.y); bp[6]=f2tf(b1.z); bp[7]=f2tf(b1.w);
        }
        __syncthreads();
        stage ^= 1;
    }

    // epilogue
    #pragma unroll
    for (int mt = 0; mt < 4; mt++) {
        int row0 = bm + wrow*64 + mt*16 + g;
        #pragma unroll
        for (int nt = 0; nt < 4; nt++) {
            int col = bn + wcol*32 + nt*8 + 2*tid4;
            float bx = 0.f, by = 0.f;
            if (BIAS) { bx = bias[col]; by = bias[col+1]; }
            float2 o01 = make_float2(acc[mt][nt][0] + bx, acc[mt][nt][1] + by);
            float2 o23 = make_float2(acc[mt][nt][2] + bx, acc[mt][nt][3] + by);
            *(float2*)&C[(size_t)row0 * N + col]       = o01;
            *(float2*)&C[(size_t)(row0 + 8) * N + col] = o23;
        }
    }
}

template<bool BIAS>
__global__ __launch_bounds__(256) void gemm_tf32(const float* __restrict__ A,
                                                 const float* __restrict__ Bm,
                                                 const float* __restrict__ bias,
                                                 float* __restrict__ C,
                                                 int M, int N, int K)
{
    __shared__ uint32_t As[2*AS_ELEMS];
    __shared__ uint32_t Bs[2*BS_ELEMS];
    gemm_tf32_body<BIAS>(A, Bm, bias, C, M, N, K,
                         blockIdx.y*128, blockIdx.x*128, As, Bs);
}

__global__ __launch_bounds__(256) void gemm_tf32_kv(const float* __restrict__ ctx,
                                                    const float* __restrict__ Wk,
                                                    const float* __restrict__ Wv,
                                                    float* __restrict__ Kp,
                                                    float* __restrict__ Vp)
{
    __shared__ uint32_t As[2*AS_ELEMS];
    __shared__ uint32_t Bs[2*BS_ELEMS];
    const float* Bm = blockIdx.z ? Wv : Wk;
    float*       C  = blockIdx.z ? Vp : Kp;
    gemm_tf32_body<false>(ctx, Bm, nullptr, C, B_*NKV, II, CK,
                          blockIdx.y*128, blockIdx.x*128, As, Bs);
}

// ============================================================================
// TF32 flash attention.
// CTA: 128 q-rows, 256 thr (8 warps), warp = 16 q x full 128-kv tile.
// Q frags live in registers entire kernel. P overwrites K's smem (tf32).
// smem (uint32): QV buffer 128x68 (Q then V), KP buffer: K 128x68 / P 128x132.
// ============================================================================
#define QV_STRIDE 68
#define PS_STRIDE 132
#define QV_ELEMS (128*QV_STRIDE)              // 8704
#define KP_ELEMS (128*PS_STRIDE)              // 16896
#define ATT_SMEM ((QV_ELEMS + KP_ELEMS) * 4)  // 102400 B

__global__ __launch_bounds__(256, 1) void attn_tf32(const float* __restrict__ Qg,
                                                    const float* __restrict__ Kg,
                                                    const float* __restrict__ Vg,
                                                    float* __restrict__ AO)
{
    extern __shared__ uint32_t smu[];
    uint32_t* QVs = smu;               // Q first, then V reuses
    uint32_t* KPs = smu + QV_ELEMS;    // K (stride 68 region reinterpreted) / P stride 132

    const int t    = threadIdx.x;
    const int lane = t & 31;
    const int w    = t >> 5;          // 0..7 -> q rows [w*16, w*16+16)
    const int g    = lane >> 2;       // 0..7
    const int tid4 = lane & 3;        // 0..3

    const int bh = blockIdx.y;
    const int b  = bh >> 3;
    const int h  = bh & 7;
    const int q0 = blockIdx.x * 128;

    // ---- load Q tile (128x64), scale, tf32, to smem ----
    #pragma unroll
    for (int j = 0; j < 8; j++) {
        int idx  = t + j*256;         // 0..2047
        int qrow = idx >> 4;
        int d    = (idx & 15) * 4;
        float4 v = *(const float4*)&Qg[((size_t)(b*NQ + q0 + qrow))*II + h*DD + d];
        uint32_t* p = &QVs[qrow*QV_STRIDE + d];
        p[0] = f2tf(v.x * SCALE);
        p[1] = f2tf(v.y * SCALE);
        p[2] = f2tf(v.z * SCALE);
        p[3] = f2tf(v.w * SCALE);
    }
    __syncthreads();

    // ---- extract Q fragments into registers (held all kernel) ----
    uint32_t qa[8][4];
    {
        int r0 = (w*16 + g) * QV_STRIDE;
        int r1 = (w*16 + g + 8) * QV_STRIDE;
        #pragma unroll
        for (int ks = 0; ks < 8; ks++) {
            int cidx = ks*8 + tid4;
            qa[ks][0] = QVs[r0 + cidx];
            qa[ks][1] = QVs[r1 + cidx];
            qa[ks][2] = QVs[r0 + cidx + 4];
            qa[ks][3] = QVs[r1 + cidx + 4];
        }
    }
    __syncthreads();   // Q region about to be reused for V

    float ofrag[8][4];
    #pragma unroll
    for (int dt = 0; dt < 8; dt++)
        #pragma unroll
        for (int e = 0; e < 4; e++) ofrag[dt][e] = 0.f;
    float m0 = -1e30f, m1 = -1e30f, l0 = 0.f, l1 = 0.f;

    for (int kv0 = 0; kv0 < NKV; kv0 += 128) {
        // ---- load K -> KPs (stride 68 layout), V -> QVs ----
        #pragma unroll
        for (int j = 0; j < 8; j++) {
            int idx   = t + j*256;
            int kvrow = idx >> 4;
            int d     = (idx & 15) * 4;
            size_t grow = ((size_t)(b*NKV + kv0 + kvrow))*II + h*DD + d;
            float4 kvl = *(const float4*)&Kg[grow];
            uint32_t* kp = &KPs[kvrow*QV_STRIDE + d];
            kp[0]=f2tf(kvl.x); kp[1]=f2tf(kvl.y); kp[2]=f2tf(kvl.z); kp[3]=f2tf(kvl.w);
            float4 vvl = *(const float4*)&Vg[grow];
            uint32_t* vp = &QVs[kvrow*QV_STRIDE + d];
            vp[0]=f2tf(vvl.x); vp[1]=f2tf(vvl.y); vp[2]=f2tf(vvl.z); vp[3]=f2tf(vvl.w);
        }
        __syncthreads();

        // ---- S = Q K^T : 16 n-tiles of 8 kv cols each ----
        float sfrag[16][4];
        #pragma unroll
        for (int nt = 0; nt < 16; nt++) {
            sfrag[nt][0]=0.f; sfrag[nt][1]=0.f; sfrag[nt][2]=0.f; sfrag[nt][3]=0.f;
            int kvrow = (nt*8 + g) * QV_STRIDE;
            #pragma unroll
            for (int ks = 0; ks < 8; ks++) {
                uint32_t bf[2];
                bf[0] = KPs[kvrow + ks*8 + tid4];
                bf[1] = KPs[kvrow + ks*8 + tid4 + 4];
                mma_tf32(sfrag[nt], qa[ks], bf);
            }
        }

        // ---- online softmax (rows r0 = w*16+g, r1 = r0+8) ----
        float tm0 = sfrag[0][0], tm1 = sfrag[0][2];
        #pragma unroll
        for (int nt = 0; nt < 16; nt++) {
            tm0 = fmaxf(tm0, fmaxf(sfrag[nt][0], sfrag[nt][1]));
            tm1 = fmaxf(tm1, fmaxf(sfrag[nt][2], sfrag[nt][3]));
        }
        tm0 = fmaxf(tm0, __shfl_xor_sync(0xffffffffu, tm0, 1));
        tm0 = fmaxf(tm0, __shfl_xor_sync(0xffffffffu, tm0, 2));
        tm1 = fmaxf(tm1, __shfl_xor_sync(0xffffffffu, tm1, 1));
        tm1 = fmaxf(tm1, __shfl_xor_sync(0xffffffffu, tm1, 2));
        float mn0 = fmaxf(m0, tm0), mn1 = fmaxf(m1, tm1);
        float al0 = __expf(m0 - mn0), al1 = __expf(m1 - mn1);
        m0 = mn0; m1 = mn1;
        float sum0 = 0.f, sum1 = 0.f;
        #pragma unroll
        for (int nt = 0; nt < 16; nt++) {
            sfrag[nt][0] = __expf(sfrag[nt][0] - mn0);
            sfrag[nt][1] = __expf(sfrag[nt][1] - mn0);
            sfrag[nt][2] = __expf(sfrag[nt][2] - mn1);
            sfrag[nt][3] = __expf(sfrag[nt][3] - mn1);
            sum0 += sfrag[nt][0] + sfrag[nt][1];
            sum1 += sfrag[nt][2] + sfrag[nt][3];
        }
        sum0 += __shfl_xor_sync(0xffffffffu, sum0, 1);
        sum0 += __shfl_xor_sync(0xffffffffu, sum0, 2);
        sum1 += __shfl_xor_sync(0xffffffffu, sum1, 1);
        sum1 += __shfl_xor_sync(0xffffffffu, sum1, 2);
        l0 = l0*al0 + sum0;
        l1 = l1*al1 + sum1;

        __syncthreads();   // done reading K; P will overwrite

        // ---- store P (tf32) into KPs with stride 132 ----
        {
            int r0 = (w*16 + g) * PS_STRIDE;
            int r1 = (w*16 + g + 8) * PS_STRIDE;
            #pragma unroll
            for (int nt = 0; nt < 16; nt++) {
                int c = nt*8 + 2*tid4;
                uint2 p0 = make_uint2(f2tf(sfrag[nt][0]), f2tf(sfrag[nt][1]));
                uint2 p1 = make_uint2(f2tf(sfrag[nt][2]), f2tf(sfrag[nt][3]));
                *(uint2*)&KPs[r0 + c] = p0;
                *(uint2*)&KPs[r1 + c] = p1;
            }
        }
        // rescale O accumulators
        #pragma unroll
        for (int dt = 0; dt < 8; dt++) {
            ofrag[dt][0] *= al0; ofrag[dt][1] *= al0;
            ofrag[dt][2] *= al1; ofrag[dt][3] *= al1;
        }
        __syncthreads();

        // ---- O += P @ V ----
        {
            int pr0 = (w*16 + g) * PS_STRIDE;
            int pr1 = (w*16 + g + 8) * PS_STRIDE;
            #pragma unroll
            for (int ks = 0; ks < 16; ks++) {
                uint32_t pa[4];
                int c = ks*8 + tid4;
                pa[0] = KPs[pr0 + c];
                pa[1] = KPs[pr1 + c];
                pa[2] = KPs[pr0 + c + 4];
                pa[3] = KPs[pr1 + c + 4];
                int vr0 = (ks*8 + tid4) * QV_STRIDE;
                int vr1 = (ks*8 + tid4 + 4) * QV_STRIDE;
                #pragma unroll
                for (int dt = 0; dt < 8; dt++) {
                    uint32_t vb[2];
                    vb[0] = QVs[vr0 + dt*8 + g];
                    vb[1] = QVs[vr1 + dt*8 + g];
                    mma_tf32(ofrag[dt], pa, vb);
                }
            }
        }
        __syncthreads();   // protect KPs/QVs before next tile's loads
    }

    // ---- normalize + store ----
    float inv0 = 1.0f / l0, inv1 = 1.0f / l1;
    int r0 = b*NQ + q0 + w*16 + g;
    #pragma unroll
    for (int dt = 0; dt < 8; dt++) {
        int col = dt*8 + 2*tid4;
        float2 o0 = make_float2(ofrag[dt][0]*inv0, ofrag[dt][1]*inv0);
        float2 o1 = make_float2(ofrag[dt][2]*inv1, ofrag[dt][3]*inv1);
        *(float2*)&AO[(size_t)r0*II + h*DD + col]       = o0;
        *(float2*)&AO[(size_t)(r0 + 8)*II + h*DD + col] = o1;
    }
}

// ============================================================================
// launch
// ============================================================================
extern "C" void kernel_launch(void* const* d_in, const int* in_sizes, int n_in,
                              void* d_out, int out_size)
{
    const float* x   = (const float*)d_in[0];
    const float* ctx = (const float*)d_in[1];
    const float* Wq  = (const float*)d_in[2];
    const float* Wk  = (const float*)d_in[3];
    const float* Wv  = (const float*)d_in[4];
    const float* Wo  = (const float*)d_in[5];
    const float* bo  = (const float*)d_in[6];
    float* out = (float*)d_out;

    float *Qp, *Kp, *Vp, *AOp;
    cudaGetSymbolAddress((void**)&Qp,  g_Q);
    cudaGetSymbolAddress((void**)&Kp,  g_K);
    cudaGetSymbolAddress((void**)&Vp,  g_V);
    cudaGetSymbolAddress((void**)&AOp, g_AO);

    dim3 blk(256);

    // Q projection: 4096x512, K=1024
    gemm_tf32<false><<<dim3(II/128, (B_*NQ)/128), blk>>>(x, Wq, nullptr, Qp, B_*NQ, II, CQ);
    // K+V projections: 2 x (4096x512, K=768)
    gemm_tf32_kv<<<dim3(II/128, (B_*NKV)/128, 2), blk>>>(ctx, Wk, Wv, Kp, Vp);

    // attention: 16 q-tiles x 16 (b,h)
    cudaFuncSetAttribute(attn_tf32, cudaFuncAttributeMaxDynamicSharedMemorySize, ATT_SMEM);
    attn_tf32<<<dim3(NQ/128, B_*HH), blk, ATT_SMEM>>>(Qp, Kp, Vp, AOp);

    // output projection + bias: 4096x1024, K=512
    gemm_tf32<true><<<dim3(CQ/128, (B_*NQ)/128), blk>>>(AOp, Wo, bo, out, B_*NQ, CQ, II);
}

// round 5
// speedup vs baseline: 2.7645x; 1.0499x over previous
#include <cuda_runtime.h>
#include <math.h>
#include <stdint.h>

// ---------------- problem constants ----------------
#define B_   2
#define NQ   2048
#define NKV  2048
#define CQ   1024
#define CK   768
#define HH   8
#define DD   64
#define II   (HH*DD)          // 512
#define SCALE 0.125f

// ---------------- scratch (Q/K/V hold tf32 bit patterns) ----------------
__device__ uint32_t g_Q [B_*NQ *II];
__device__ uint32_t g_K [B_*NKV*II];
__device__ uint32_t g_V [B_*NKV*II];
__device__ float    g_AO[B_*NQ *II];

// ---------------- helpers ----------------
__device__ __forceinline__ uint32_t f2tf(float f) {
    uint32_t u;
    asm("cvt.rna.tf32.f32 %0, %1;" : "=r"(u) : "f"(f));
    return u;
}
__device__ __forceinline__ void mma_tf32(float c[4], const uint32_t a[4], const uint32_t b[2]) {
    asm("mma.sync.aligned.m16n8k8.row.col.f32.tf32.tf32.f32 "
        "{%0,%1,%2,%3},{%4,%5,%6,%7},{%8,%9},{%0,%1,%2,%3};"
        : "+f"(c[0]), "+f"(c[1]), "+f"(c[2]), "+f"(c[3])
        : "r"(a[0]), "r"(a[1]), "r"(a[2]), "r"(a[3]), "r"(b[0]), "r"(b[1]));
}
__device__ __forceinline__ void cp16(void* sptr, const void* gptr) {
    uint32_t sa = (uint32_t)__cvta_generic_to_shared(sptr);
    asm volatile("cp.async.cg.shared.global [%0], [%1], 16;" :: "r"(sa), "l"(gptr));
}
#define CP_COMMIT() asm volatile("cp.async.commit_group;")
#define CP_WAIT0()  asm volatile("cp.async.wait_group 0;" ::: "memory")

// ============================================================================
// TF32 GEMM body: CTA 128x128, BK=16, 8 warps (2x4), warp 64x32.
// TF32OUT: write tf32 bits (uint32), scaled by oscale. Else fp32 (+bias).
// ============================================================================
#define AS_STRIDE 20
#define BS_STRIDE 132
#define AS_ELEMS (128*AS_STRIDE)
#define BS_ELEMS (16*BS_STRIDE)

template<bool BIAS, bool TF32OUT>
__device__ __forceinline__ void gemm_tf32_body(const float* __restrict__ A,
                                               const float* __restrict__ Bm,
                                               const float* __restrict__ bias,
                                               void* __restrict__ Cv,
                                               int M, int N, int K,
                                               int bm, int bn, float oscale,
                                               uint32_t* As, uint32_t* Bs)
{
    const int t    = threadIdx.x;
    const int lane = t & 31;
    const int w    = t >> 5;
    const int wrow = w >> 2;
    const int wcol = w & 3;
    const int g    = lane >> 2;
    const int tid4 = lane & 3;

    const int arow  = t >> 1;
    const int acol0 = (t & 1) * 8;
    const int brow  = t >> 4;
    const int bcol0 = (t & 15) * 8;

    const float* Aptr = A + (size_t)(bm + arow) * K + acol0;
    const float* Bptr = Bm + (size_t)brow * N + bn + bcol0;

    float acc[4][4][4];
    #pragma unroll
    for (int mt = 0; mt < 4; mt++)
        #pragma unroll
        for (int nt = 0; nt < 4; nt++)
            #pragma unroll
            for (int e = 0; e < 4; e++) acc[mt][nt][e] = 0.f;

    float4 a0 = *(const float4*)(Aptr);
    float4 a1 = *(const float4*)(Aptr + 4);
    float4 b0 = *(const float4*)(Bptr);
    float4 b1 = *(const float4*)(Bptr + 4);
    {
        uint32_t* ap = &As[arow*AS_STRIDE + acol0];
        ap[0]=f2tf(a0.x); ap[1]=f2tf(a0.y); ap[2]=f2tf(a0.z); ap[3]=f2tf(a0.w);
        ap[4]=f2tf(a1.x); ap[5]=f2tf(a1.y); ap[6]=f2tf(a1.z); ap[7]=f2tf(a1.w);
        uint32_t* bp = &Bs[brow*BS_STRIDE + bcol0];
        bp[0]=f2tf(b0.x); bp[1]=f2tf(b0.y); bp[2]=f2tf(b0.z); bp[3]=f2tf(b0.w);
        bp[4]=f2tf(b1.x); bp[5]=f2tf(b1.y); bp[6]=f2tf(b1.z); bp[7]=f2tf(b1.w);
    }
    __syncthreads();

    int stage = 0;
    for (int kb = 0; kb < K; kb += 16) {
        const bool more = (kb + 16) < K;
        if (more) {
            a0 = *(const float4*)(Aptr + kb + 16);
            a1 = *(const float4*)(Aptr + kb + 20);
            b0 = *(const float4*)(Bptr + (size_t)(kb + 16) * N);
            b1 = *(const float4*)(Bptr + (size_t)(kb + 16) * N + 4);
        }

        const uint32_t* Asc = As + stage * AS_ELEMS;
        const uint32_t* Bsc = Bs + stage * BS_ELEMS;

        #pragma unroll
        for (int ks = 0; ks < 2; ks++) {
            uint32_t af[4][4], bf[4][2];
            #pragma unroll
            for (int mt = 0; mt < 4; mt++) {
                int r = (wrow*64 + mt*16 + g) * AS_STRIDE + ks*8 + tid4;
                af[mt][0] = Asc[r];
                af[mt][1] = Asc[r + 8*AS_STRIDE];
                af[mt][2] = Asc[r + 4];
                af[mt][3] = Asc[r + 8*AS_STRIDE + 4];
            }
            #pragma unroll
            for (int nt = 0; nt < 4; nt++) {
                int cidx = wcol*32 + nt*8 + g;
                bf[nt][0] = Bsc[(ks*8 + tid4)*BS_STRIDE + cidx];
                bf[nt][1] = Bsc[(ks*8 + tid4 + 4)*BS_STRIDE + cidx];
            }
            #pragma unroll
            for (int mt = 0; mt < 4; mt++)
                #pragma unroll
                for (int nt = 0; nt < 4; nt++)
                    mma_tf32(acc[mt][nt], af[mt], bf[nt]);
        }

        if (more) {
            uint32_t* Asn = As + (stage ^ 1) * AS_ELEMS;
            uint32_t* Bsn = Bs + (stage ^ 1) * BS_ELEMS;
            uint32_t* ap = &Asn[arow*AS_STRIDE + acol0];
            ap[0]=f2tf(a0.x); ap[1]=f2tf(a0.y); ap[2]=f2tf(a0.z); ap[3]=f2tf(a0.w);
            ap[4]=f2tf(a1.x); ap[5]=f2tf(a1.y); ap[6]=f2tf(a1.z); ap[7]=f2tf(a1.w);
            uint32_t* bp = &Bsn[brow*BS_STRIDE + bcol0];
            bp[0]=f2tf(b0.x); bp[1]=f2tf(b0.y); bp[2]=f2tf(b0.z); bp[3]=f2tf(b0.w);
            bp[4]=f2tf(b1.x); bp[5]=f2tf(b1.y); bp[6]=f2tf(b1.z); bp[7]=f2tf(b1.w);
        }
        __syncthreads();
        stage ^= 1;
    }

    #pragma unroll
    for (int mt = 0; mt < 4; mt++) {
        int row0 = bm + wrow*64 + mt*16 + g;
        #pragma unroll
        for (int nt = 0; nt < 4; nt++) {
            int col = bn + wcol*32 + nt*8 + 2*tid4;
            if (TF32OUT) {
                uint32_t* C = (uint32_t*)Cv;
                uint2 o01 = make_uint2(f2tf(acc[mt][nt][0]*oscale), f2tf(acc[mt][nt][1]*oscale));
                uint2 o23 = make_uint2(f2tf(acc[mt][nt][2]*oscale), f2tf(acc[mt][nt][3]*oscale));
                *(uint2*)&C[(size_t)row0 * N + col]       = o01;
                *(uint2*)&C[(size_t)(row0 + 8) * N + col] = o23;
            } else {
                float* C = (float*)Cv;
                float bx = 0.f, by = 0.f;
                if (BIAS) { bx = bias[col]; by = bias[col+1]; }
                float2 o01 = make_float2(acc[mt][nt][0] + bx, acc[mt][nt][1] + by);
                float2 o23 = make_float2(acc[mt][nt][2] + bx, acc[mt][nt][3] + by);
                *(float2*)&C[(size_t)row0 * N + col]       = o01;
                *(float2*)&C[(size_t)(row0 + 8) * N + col] = o23;
            }
        }
    }
}

// fused Q/K/V projections: z=0 -> Q (scaled), z=1 -> K, z=2 -> V
__global__ __launch_bounds__(256) void gemm_proj(const float* __restrict__ x,
                                                 const float* __restrict__ ctx,
                                                 const float* __restrict__ Wq,
                                                 const float* __restrict__ Wk,
                                                 const float* __restrict__ Wv,
                                                 uint32_t* __restrict__ Qp,
                                                 uint32_t* __restrict__ Kp,
                                                 uint32_t* __restrict__ Vp)
{
    __shared__ uint32_t As[2*AS_ELEMS];
    __shared__ uint32_t Bs[2*BS_ELEMS];
    const int z = blockIdx.z;
    const float* A  = (z == 0) ? x  : ctx;
    const float* Bm = (z == 0) ? Wq : ((z == 1) ? Wk : Wv);
    uint32_t*    C  = (z == 0) ? Qp : ((z == 1) ? Kp : Vp);
    const int    K  = (z == 0) ? CQ : CK;
    const float  sc = (z == 0) ? SCALE : 1.0f;
    gemm_tf32_body<false, true>(A, Bm, nullptr, C, B_*NQ, II, K,
                                blockIdx.y*128, blockIdx.x*128, sc, As, Bs);
}

// output projection (fp32 out + bias)
__global__ __launch_bounds__(256) void gemm_out(const float* __restrict__ A,
                                                const float* __restrict__ Bm,
                                                const float* __restrict__ bias,
                                                float* __restrict__ C)
{
    __shared__ uint32_t As[2*AS_ELEMS];
    __shared__ uint32_t Bs[2*BS_ELEMS];
    gemm_tf32_body<true, false>(A, Bm, bias, C, B_*NQ, CQ, II,
                                blockIdx.y*128, blockIdx.x*128, 1.0f, As, Bs);
}

// ============================================================================
// TF32 flash attention. Inputs already tf32 bits (Q pre-scaled).
// CTA: 128 q x 128 kv tiles, 256 thr, warp = 16 q x full kv tile.
// cp.async tile loads. P overwrites K smem. 2 CTAs/SM.
// ============================================================================
#define QV_STRIDE 68
#define PS_STRIDE 132
#define QV_ELEMS (128*QV_STRIDE)
#define KP_ELEMS (128*PS_STRIDE)
#define ATT_SMEM ((QV_ELEMS + KP_ELEMS) * 4)   // 102400 B

__global__ __launch_bounds__(256, 2) void attn_tf32(const uint32_t* __restrict__ Qg,
                                                    const uint32_t* __restrict__ Kg,
                                                    const uint32_t* __restrict__ Vg,
                                                    float* __restrict__ AO)
{
    extern __shared__ uint32_t smu[];
    uint32_t* QVs = smu;               // Q, then V
    uint32_t* KPs = smu + QV_ELEMS;    // K (stride 68) / P (stride 132)

    const int t    = threadIdx.x;
    const int lane = t & 31;
    const int w    = t >> 5;
    const int g    = lane >> 2;
    const int tid4 = lane & 3;

    const int bh = blockIdx.y;
    const int b  = bh >> 3;
    const int h  = bh & 7;
    const int q0 = blockIdx.x * 128;

    // ---- Q tile via cp.async ----
    #pragma unroll
    for (int j = 0; j < 8; j++) {
        int idx  = t + j*256;
        int qrow = idx >> 4;
        int d    = (idx & 15) * 4;
        cp16(&QVs[qrow*QV_STRIDE + d], &Qg[(size_t)(b*NQ + q0 + qrow)*II + h*DD + d]);
    }
    CP_COMMIT(); CP_WAIT0();
    __syncthreads();

    uint32_t qa[8][4];
    {
        int r0 = (w*16 + g) * QV_STRIDE;
        int r1 = (w*16 + g + 8) * QV_STRIDE;
        #pragma unroll
        for (int ks = 0; ks < 8; ks++) {
            int cidx = ks*8 + tid4;
            qa[ks][0] = QVs[r0 + cidx];
            qa[ks][1] = QVs[r1 + cidx];
            qa[ks][2] = QVs[r0 + cidx + 4];
            qa[ks][3] = QVs[r1 + cidx + 4];
        }
    }
    __syncthreads();   // Q region about to be reused for V

    float ofrag[8][4];
    #pragma unroll
    for (int dt = 0; dt < 8; dt++)
        #pragma unroll
        for (int e = 0; e < 4; e++) ofrag[dt][e] = 0.f;
    float m0 = -1e30f, m1 = -1e30f, l0 = 0.f, l1 = 0.f;

    for (int kv0 = 0; kv0 < NKV; kv0 += 128) {
        // ---- K -> KPs (stride 68), V -> QVs, both cp.async ----
        #pragma unroll
        for (int j = 0; j < 8; j++) {
            int idx   = t + j*256;
            int kvrow = idx >> 4;
            int d     = (idx & 15) * 4;
            size_t grow = (size_t)(b*NKV + kv0 + kvrow)*II + h*DD + d;
            cp16(&KPs[kvrow*QV_STRIDE + d], &Kg[grow]);
            cp16(&QVs[kvrow*QV_STRIDE + d], &Vg[grow]);
        }
        CP_COMMIT(); CP_WAIT0();
        __syncthreads();

        // ---- S = Q K^T ----
        float sfrag[16][4];
        #pragma unroll
        for (int nt = 0; nt < 16; nt++) {
            sfrag[nt][0]=0.f; sfrag[nt][1]=0.f; sfrag[nt][2]=0.f; sfrag[nt][3]=0.f;
            int kvrow = (nt*8 + g) * QV_STRIDE;
            #pragma unroll
            for (int ks = 0; ks < 8; ks++) {
                uint32_t bf[2];
                bf[0] = KPs[kvrow + ks*8 + tid4];
                bf[1] = KPs[kvrow + ks*8 + tid4 + 4];
                mma_tf32(sfrag[nt], qa[ks], bf);
            }
        }

        // ---- online softmax ----
        float tm0 = sfrag[0][0], tm1 = sfrag[0][2];
        #pragma unroll
        for (int nt = 0; nt < 16; nt++) {
            tm0 = fmaxf(tm0, fmaxf(sfrag[nt][0], sfrag[nt][1]));
            tm1 = fmaxf(tm1, fmaxf(sfrag[nt][2], sfrag[nt][3]));
        }
        tm0 = fmaxf(tm0, __shfl_xor_sync(0xffffffffu, tm0, 1));
        tm0 = fmaxf(tm0, __shfl_xor_sync(0xffffffffu, tm0, 2));
        tm1 = fmaxf(tm1, __shfl_xor_sync(0xffffffffu, tm1, 1));
        tm1 = fmaxf(tm1, __shfl_xor_sync(0xffffffffu, tm1, 2));
        float mn0 = fmaxf(m0, tm0), mn1 = fmaxf(m1, tm1);
        float al0 = __expf(m0 - mn0), al1 = __expf(m1 - mn1);
        m0 = mn0; m1 = mn1;
        float sum0 = 0.f, sum1 = 0.f;
        #pragma unroll
        for (int nt = 0; nt < 16; nt++) {
            sfrag[nt][0] = __expf(sfrag[nt][0] - mn0);
            sfrag[nt][1] = __expf(sfrag[nt][1] - mn0);
            sfrag[nt][2] = __expf(sfrag[nt][2] - mn1);
            sfrag[nt][3] = __expf(sfrag[nt][3] - mn1);
            sum0 += sfrag[nt][0] + sfrag[nt][1];
            sum1 += sfrag[nt][2] + sfrag[nt][3];
        }
        sum0 += __shfl_xor_sync(0xffffffffu, sum0, 1);
        sum0 += __shfl_xor_sync(0xffffffffu, sum0, 2);
        sum1 += __shfl_xor_sync(0xffffffffu, sum1, 1);
        sum1 += __shfl_xor_sync(0xffffffffu, sum1, 2);
        l0 = l0*al0 + sum0;
        l1 = l1*al1 + sum1;

        __syncthreads();   // done reading K

        // ---- P -> KPs (stride 132, tf32) ----
        {
            int r0 = (w*16 + g) * PS_STRIDE;
            int r1 = (w*16 + g + 8) * PS_STRIDE;
            #pragma unroll
            for (int nt = 0; nt < 16; nt++) {
                int c = nt*8 + 2*tid4;
                *(uint2*)&KPs[r0 + c] = make_uint2(f2tf(sfrag[nt][0]), f2tf(sfrag[nt][1]));
                *(uint2*)&KPs[r1 + c] = make_uint2(f2tf(sfrag[nt][2]), f2tf(sfrag[nt][3]));
            }
        }
        #pragma unroll
        for (int dt = 0; dt < 8; dt++) {
            ofrag[dt][0] *= al0; ofrag[dt][1] *= al0;
            ofrag[dt][2] *= al1; ofrag[dt][3] *= al1;
        }
        __syncthreads();

        // ---- O += P @ V ----
        {
            int pr0 = (w*16 + g) * PS_STRIDE;
            int pr1 = (w*16 + g + 8) * PS_STRIDE;
            #pragma unroll
            for (int ks = 0; ks < 16; ks++) {
                uint32_t pa[4];
                int c = ks*8 + tid4;
                pa[0] = KPs[pr0 + c];
                pa[1] = KPs[pr1 + c];
                pa[2] = KPs[pr0 + c + 4];
                pa[3] = KPs[pr1 + c + 4];
                int vr0 = (ks*8 + tid4) * QV_STRIDE;
                int vr1 = (ks*8 + tid4 + 4) * QV_STRIDE;
                #pragma unroll
                for (int dt = 0; dt < 8; dt++) {
                    uint32_t vb[2];
                    vb[0] = QVs[vr0 + dt*8 + g];
                    vb[1] = QVs[vr1 + dt*8 + g];
                    mma_tf32(ofrag[dt], pa, vb);
                }
            }
        }
        __syncthreads();
    }

    // ---- normalize + store ----
    float inv0 = 1.0f / l0, inv1 = 1.0f / l1;
    int r0 = b*NQ + q0 + w*16 + g;
    #pragma unroll
    for (int dt = 0; dt < 8; dt++) {
        int col = dt*8 + 2*tid4;
        *(float2*)&AO[(size_t)r0*II + h*DD + col]       = make_float2(ofrag[dt][0]*inv0, ofrag[dt][1]*inv0);
        *(float2*)&AO[(size_t)(r0 + 8)*II + h*DD + col] = make_float2(ofrag[dt][2]*inv1, ofrag[dt][3]*inv1);
    }
}

// ============================================================================
// launch
// ============================================================================
extern "C" void kernel_launch(void* const* d_in, const int* in_sizes, int n_in,
                              void* d_out, int out_size)
{
    const float* x   = (const float*)d_in[0];
    const float* ctx = (const float*)d_in[1];
    const float* Wq  = (const float*)d_in[2];
    const float* Wk  = (const float*)d_in[3];
    const float* Wv  = (const float*)d_in[4];
    const float* Wo  = (const float*)d_in[5];
    const float* bo  = (const float*)d_in[6];
    float* out = (float*)d_out;

    uint32_t *Qp, *Kp, *Vp;
    float *AOp;
    cudaGetSymbolAddress((void**)&Qp,  g_Q);
    cudaGetSymbolAddress((void**)&Kp,  g_K);
    cudaGetSymbolAddress((void**)&Vp,  g_V);
    cudaGetSymbolAddress((void**)&AOp, g_AO);

    dim3 blk(256);

    // fused Q/K/V projections (Q pre-scaled, all tf32-out)
    gemm_proj<<<dim3(II/128, (B_*NQ)/128, 3), blk>>>(x, ctx, Wq, Wk, Wv, Qp, Kp, Vp);

    // attention
    cudaFuncSetAttribute(attn_tf32, cudaFuncAttributeMaxDynamicSharedMemorySize, ATT_SMEM);
    attn_tf32<<<dim3(NQ/128, B_*HH), blk, ATT_SMEM>>>(Qp, Kp, Vp, AOp);

    // output projection + bias
    gemm_out<<<dim3(CQ/128, (B_*NQ)/128), blk>>>(AOp, Wo, bo, out);
}

// round 6
// speedup vs baseline: 3.3807x; 1.2229x over previous
#include <cuda_runtime.h>
#include <math.h>
#include <stdint.h>

// ---------------- problem constants ----------------
#define B_   2
#define NQ   2048
#define NKV  2048
#define CQ   1024
#define CK   768
#define HH   8
#define DD   64
#define II   (HH*DD)          // 512
#define SCALE 0.125f

// ---------------- scratch ----------------
// g_Q, g_K: tf32 bits, cols pair-permuted within 8-groups ([0,4,1,5,2,6,3,7])
// g_V: tf32 bits, natural layout
__device__ uint32_t g_Q [B_*NQ *II];
__device__ uint32_t g_K [B_*NKV*II];
__device__ uint32_t g_V [B_*NKV*II];
__device__ float    g_AO[B_*NQ *II];

// ---------------- helpers ----------------
__device__ __forceinline__ uint32_t f2tf(float f) {
    uint32_t u;
    asm("cvt.rna.tf32.f32 %0, %1;" : "=r"(u) : "f"(f));
    return u;
}
__device__ __forceinline__ void mma_tf32(float c[4], const uint32_t a[4], const uint32_t b[2]) {
    asm("mma.sync.aligned.m16n8k8.row.col.f32.tf32.tf32.f32 "
        "{%0,%1,%2,%3},{%4,%5,%6,%7},{%8,%9},{%0,%1,%2,%3};"
        : "+f"(c[0]), "+f"(c[1]), "+f"(c[2]), "+f"(c[3])
        : "r"(a[0]), "r"(a[1]), "r"(a[2]), "r"(a[3]), "r"(b[0]), "r"(b[1]));
}
__device__ __forceinline__ void cp16(void* sptr, const void* gptr) {
    uint32_t sa = (uint32_t)__cvta_generic_to_shared(sptr);
    asm volatile("cp.async.cg.shared.global [%0], [%1], 16;" :: "r"(sa), "l"(gptr));
}
#define CP_COMMIT() asm volatile("cp.async.commit_group;")

// pair-permute a column index within its 8-group: [0,4,1,5,2,6,3,7]
__device__ __forceinline__ int pcol(int c) {
    return (c & ~7) | ((c & 3) << 1) | ((c & 7) >> 2);
}

// ============================================================================
// TF32 GEMM: CTA 128x128, BK=16, 8 warps (2x4), warp 64x32.
// Pair-packed smem: A rows hold (k,k+4) pairs adjacent (stride 24);
// B stored as 8 pair-rows x 128 n x 2 (stride 264). All frag loads LDS.64.
// ============================================================================
#define AS_STRIDE 24
#define AS_ELEMS (128*AS_STRIDE)   // 3072
#define BS_STRIDE 264
#define BS_ELEMS (8*BS_STRIDE)     // 2112

template<bool BIAS, bool TF32OUT>
__device__ __forceinline__ void gemm_tf32_body(const float* __restrict__ A,
                                               const float* __restrict__ Bm,
                                               const float* __restrict__ bias,
                                               void* __restrict__ Cv,
                                               int N, int K,
                                               int bm, int bn, float oscale, bool perm,
                                               uint32_t* As, uint32_t* Bs)
{
    const int t    = threadIdx.x;
    const int lane = t & 31;
    const int w    = t >> 5;
    const int wrow = w >> 2;
    const int wcol = w & 3;
    const int g    = lane >> 2;
    const int tid4 = lane & 3;

    // A global: 1 row x 8 cols per thread
    const int arow  = t >> 1;
    const int acol0 = (t & 1) * 8;
    // B global: 2 rows (k, k+4) x 4 cols per thread
    const int bpr   = t >> 5;                          // 0..7
    const int brow0 = ((bpr >> 2) << 3) + (bpr & 3);   // ks*8 + t4
    const int bn0   = (t & 31) * 4;

    const float* Aptr  = A  + (size_t)(bm + arow) * K + acol0;
    const float* Bptr0 = Bm + (size_t)brow0 * N + bn + bn0;
    const float* Bptr1 = Bptr0 + (size_t)4 * N;

    float acc[4][4][4];
    #pragma unroll
    for (int mt = 0; mt < 4; mt++)
        #pragma unroll
        for (int nt = 0; nt < 4; nt++)
            #pragma unroll
            for (int e = 0; e < 4; e++) acc[mt][nt][e] = 0.f;

    float4 a0 = *(const float4*)(Aptr);
    float4 a1 = *(const float4*)(Aptr + 4);
    float4 b0 = *(const float4*)(Bptr0);
    float4 b1 = *(const float4*)(Bptr1);
    {
        float av[8] = {a0.x,a0.y,a0.z,a0.w,a1.x,a1.y,a1.z,a1.w};
        uint32_t* ap = &As[arow*AS_STRIDE + acol0];
        #pragma unroll
        for (int i = 0; i < 4; i++)
            *(uint2*)&ap[2*i] = make_uint2(f2tf(av[i]), f2tf(av[i+4]));
        float bv0[4] = {b0.x,b0.y,b0.z,b0.w};
        float bv1[4] = {b1.x,b1.y,b1.z,b1.w};
        uint32_t* bp = &Bs[bpr*BS_STRIDE + 2*bn0];
        #pragma unroll
        for (int j = 0; j < 4; j++)
            *(uint2*)&bp[2*j] = make_uint2(f2tf(bv0[j]), f2tf(bv1[j]));
    }
    __syncthreads();

    int stage = 0;
    for (int kb = 0; kb < K; kb += 16) {
        const bool more = (kb + 16) < K;
        if (more) {
            a0 = *(const float4*)(Aptr + kb + 16);
            a1 = *(const float4*)(Aptr + kb + 20);
            b0 = *(const float4*)(Bptr0 + (size_t)(kb + 16) * N);
            b1 = *(const float4*)(Bptr1 + (size_t)(kb + 16) * N);
        }

        const uint32_t* Asc = As + stage * AS_ELEMS;
        const uint32_t* Bsc = Bs + stage * BS_ELEMS;

        #pragma unroll
        for (int ks = 0; ks < 2; ks++) {
            uint32_t af[4][4], bf[4][2];
            #pragma unroll
            for (int mt = 0; mt < 4; mt++) {
                int r = wrow*64 + mt*16 + g;
                uint2 lo = *(const uint2*)&Asc[r*AS_STRIDE + ks*8 + 2*tid4];
                uint2 hi = *(const uint2*)&Asc[(r+8)*AS_STRIDE + ks*8 + 2*tid4];
                af[mt][0] = lo.x; af[mt][1] = hi.x; af[mt][2] = lo.y; af[mt][3] = hi.y;
            }
            #pragma unroll
            for (int nt = 0; nt < 4; nt++) {
                int cidx = wcol*32 + nt*8 + g;
                uint2 bb = *(const uint2*)&Bsc[(ks*4 + tid4)*BS_STRIDE + 2*cidx];
                bf[nt][0] = bb.x; bf[nt][1] = bb.y;
            }
            #pragma unroll
            for (int mt = 0; mt < 4; mt++)
                #pragma unroll
                for (int nt = 0; nt < 4; nt++)
                    mma_tf32(acc[mt][nt], af[mt], bf[nt]);
        }

        if (more) {
            uint32_t* Asn = As + (stage ^ 1) * AS_ELEMS;
            uint32_t* Bsn = Bs + (stage ^ 1) * BS_ELEMS;
            float av[8] = {a0.x,a0.y,a0.z,a0.w,a1.x,a1.y,a1.z,a1.w};
            uint32_t* ap = &Asn[arow*AS_STRIDE + acol0];
            #pragma unroll
            for (int i = 0; i < 4; i++)
                *(uint2*)&ap[2*i] = make_uint2(f2tf(av[i]), f2tf(av[i+4]));
            float bv0[4] = {b0.x,b0.y,b0.z,b0.w};
            float bv1[4] = {b1.x,b1.y,b1.z,b1.w};
            uint32_t* bp = &Bsn[bpr*BS_STRIDE + 2*bn0];
            #pragma unroll
            for (int j = 0; j < 4; j++)
                *(uint2*)&bp[2*j] = make_uint2(f2tf(bv0[j]), f2tf(bv1[j]));
        }
        __syncthreads();
        stage ^= 1;
    }

    #pragma unroll
    for (int mt = 0; mt < 4; mt++) {
        int row0 = bm + wrow*64 + mt*16 + g;
        #pragma unroll
        for (int nt = 0; nt < 4; nt++) {
            int col = bn + wcol*32 + nt*8 + 2*tid4;
            if (TF32OUT) {
                uint32_t* C = (uint32_t*)Cv;
                uint32_t u00 = f2tf(acc[mt][nt][0]*oscale);
                uint32_t u01 = f2tf(acc[mt][nt][1]*oscale);
                uint32_t u10 = f2tf(acc[mt][nt][2]*oscale);
                uint32_t u11 = f2tf(acc[mt][nt][3]*oscale);
                if (perm) {
                    int c0 = pcol(col), c1 = pcol(col+1);
                    C[(size_t)row0 * N + c0]       = u00;
                    C[(size_t)row0 * N + c1]       = u01;
                    C[(size_t)(row0 + 8) * N + c0] = u10;
                    C[(size_t)(row0 + 8) * N + c1] = u11;
                } else {
                    *(uint2*)&C[(size_t)row0 * N + col]       = make_uint2(u00, u01);
                    *(uint2*)&C[(size_t)(row0 + 8) * N + col] = make_uint2(u10, u11);
                }
            } else {
                float* C = (float*)Cv;
                float bx = 0.f, by = 0.f;
                if (BIAS) { bx = bias[col]; by = bias[col+1]; }
                *(float2*)&C[(size_t)row0 * N + col] =
                    make_float2(acc[mt][nt][0] + bx, acc[mt][nt][1] + by);
                *(float2*)&C[(size_t)(row0 + 8) * N + col] =
                    make_float2(acc[mt][nt][2] + bx, acc[mt][nt][3] + by);
            }
        }
    }
}

// fused Q/K/V projections: z=0 -> Q (scaled, perm), z=1 -> K (perm), z=2 -> V
__global__ __launch_bounds__(256) void gemm_proj(const float* __restrict__ x,
                                                 const float* __restrict__ ctx,
                                                 const float* __restrict__ Wq,
                                                 const float* __restrict__ Wk,
                                                 const float* __restrict__ Wv,
                                                 uint32_t* __restrict__ Qp,
                                                 uint32_t* __restrict__ Kp,
                                                 uint32_t* __restrict__ Vp)
{
    __shared__ __align__(16) uint32_t As[2*AS_ELEMS];
    __shared__ __align__(16) uint32_t Bs[2*BS_ELEMS];
    const int z = blockIdx.z;
    const float* A  = (z == 0) ? x  : ctx;
    const float* Bm = (z == 0) ? Wq : ((z == 1) ? Wk : Wv);
    uint32_t*    C  = (z == 0) ? Qp : ((z == 1) ? Kp : Vp);
    const int    K  = (z == 0) ? CQ : CK;
    const float  sc = (z == 0) ? SCALE : 1.0f;
    gemm_tf32_body<false, true>(A, Bm, nullptr, C, II, K,
                                blockIdx.y*128, blockIdx.x*128, sc, z != 2, As, Bs);
}

// output projection (fp32 out + bias)
__global__ __launch_bounds__(256) void gemm_out(const float* __restrict__ A,
                                                const float* __restrict__ Bm,
                                                const float* __restrict__ bias,
                                                float* __restrict__ C)
{
    __shared__ __align__(16) uint32_t As[2*AS_ELEMS];
    __shared__ __align__(16) uint32_t Bs[2*BS_ELEMS];
    gemm_tf32_body<true, false>(A, Bm, bias, C, CQ, II,
                                blockIdx.y*128, blockIdx.x*128, 1.0f, false, As, Bs);
}

// ============================================================================
// TF32 flash attention. CTA: 128 q x 128 kv, 256 thr, warp = 16 q.
// Q/K pair-permuted in GMEM -> LDS.64 frags. P stays in registers via
// quad shfl transpose. Double-buffered K/V with cp.async prefetch.
// smem: Q[128x72] + 2x K[128x72] + 2x V[128x72] = 184320 B, 1 CTA/SM.
// ============================================================================
#define QS 72
#define ATT_T_ELEMS (128*QS)                 // 9216
#define ATT_SMEM (5*ATT_T_ELEMS*4)           // 184320 B

__global__ __launch_bounds__(256, 1) void attn_tf32(const uint32_t* __restrict__ Qg,
                                                    const uint32_t* __restrict__ Kg,
                                                    const uint32_t* __restrict__ Vg,
                                                    float* __restrict__ AO)
{
    extern __shared__ __align__(16) uint32_t smu[];
    uint32_t* Qs = smu;
    uint32_t* Kb0 = smu + ATT_T_ELEMS;
    uint32_t* Kb1 = smu + 2*ATT_T_ELEMS;
    uint32_t* Vb0 = smu + 3*ATT_T_ELEMS;
    uint32_t* Vb1 = smu + 4*ATT_T_ELEMS;

    const int t    = threadIdx.x;
    const int lane = t & 31;
    const int w    = t >> 5;
    const int g    = lane >> 2;
    const int tid4 = lane & 3;

    const int bh = blockIdx.y;
    const int b  = bh >> 3;
    const int h  = bh & 7;
    const int q0 = blockIdx.x * 128;

    // ---- prologue: Q + tile 0 (one cp.async group) ----
    #pragma unroll
    for (int j = 0; j < 8; j++) {
        int idx = t + j*256;
        int row = idx >> 4;
        int d   = (idx & 15) * 4;
        cp16(&Qs[row*QS + d],  &Qg[(size_t)(b*NQ  + q0 + row)*II + h*DD + d]);
    }
    #pragma unroll
    for (int j = 0; j < 8; j++) {
        int idx = t + j*256;
        int row = idx >> 4;
        int d   = (idx & 15) * 4;
        size_t grow = (size_t)(b*NKV + row)*II + h*DD + d;
        cp16(&Kb0[row*QS + d], &Kg[grow]);
        cp16(&Vb0[row*QS + d], &Vg[grow]);
    }
    CP_COMMIT();

    uint32_t qa[8][4];
    float ofrag[8][4];
    #pragma unroll
    for (int dt = 0; dt < 8; dt++)
        #pragma unroll
        for (int e = 0; e < 4; e++) ofrag[dt][e] = 0.f;
    float m0 = -1e30f, m1 = -1e30f, l0 = 0.f, l1 = 0.f;

    const int src0 = (lane & ~3) | (tid4 >> 1);
    const int src1 = src0 + 2;
    const bool oddl = tid4 & 1;

    for (int it = 0; it < NKV/128; it++) {
        const int cur = it & 1;
        uint32_t* Kc = cur ? Kb1 : Kb0;
        uint32_t* Vc = cur ? Vb1 : Vb0;

        if (it + 1 < NKV/128) {
            uint32_t* Kn = cur ? Kb0 : Kb1;
            uint32_t* Vn = cur ? Vb0 : Vb1;
            int kv0n = (it + 1) * 128;
            #pragma unroll
            for (int j = 0; j < 8; j++) {
                int idx = t + j*256;
                int row = idx >> 4;
                int d   = (idx & 15) * 4;
                size_t grow = (size_t)(b*NKV + kv0n + row)*II + h*DD + d;
                cp16(&Kn[row*QS + d], &Kg[grow]);
                cp16(&Vn[row*QS + d], &Vg[grow]);
            }
            CP_COMMIT();
            asm volatile("cp.async.wait_group 1;" ::: "memory");
        } else {
            asm volatile("cp.async.wait_group 0;" ::: "memory");
        }
        __syncthreads();

        if (it == 0) {
            // extract Q fragments (pair-packed -> LDS.64)
            int r0 = (w*16 + g) * QS;
            int r1 = (w*16 + g + 8) * QS;
            #pragma unroll
            for (int ks = 0; ks < 8; ks++) {
                uint2 lo = *(const uint2*)&Qs[r0 + ks*8 + 2*tid4];
                uint2 hi = *(const uint2*)&Qs[r1 + ks*8 + 2*tid4];
                qa[ks][0] = lo.x; qa[ks][1] = hi.x; qa[ks][2] = lo.y; qa[ks][3] = hi.y;
            }
        }

        // ---- S = Q K^T ----
        float sfrag[16][4];
        #pragma unroll
        for (int nt = 0; nt < 16; nt++) {
            sfrag[nt][0]=0.f; sfrag[nt][1]=0.f; sfrag[nt][2]=0.f; sfrag[nt][3]=0.f;
            int krow = (nt*8 + g) * QS;
            #pragma unroll
            for (int ks = 0; ks < 8; ks++) {
                uint2 bb = *(const uint2*)&Kc[krow + ks*8 + 2*tid4];
                uint32_t bf[2] = {bb.x, bb.y};
                mma_tf32(sfrag[nt], qa[ks], bf);
            }
        }

        // ---- online softmax (quad reduction) ----
        float tm0 = sfrag[0][0], tm1 = sfrag[0][2];
        #pragma unroll
        for (int nt = 0; nt < 16; nt++) {
            tm0 = fmaxf(tm0, fmaxf(sfrag[nt][0], sfrag[nt][1]));
            tm1 = fmaxf(tm1, fmaxf(sfrag[nt][2], sfrag[nt][3]));
        }
        tm0 = fmaxf(tm0, __shfl_xor_sync(0xffffffffu, tm0, 1));
        tm0 = fmaxf(tm0, __shfl_xor_sync(0xffffffffu, tm0, 2));
        tm1 = fmaxf(tm1, __shfl_xor_sync(0xffffffffu, tm1, 1));
        tm1 = fmaxf(tm1, __shfl_xor_sync(0xffffffffu, tm1, 2));
        float mn0 = fmaxf(m0, tm0), mn1 = fmaxf(m1, tm1);
        float al0 = __expf(m0 - mn0), al1 = __expf(m1 - mn1);
        m0 = mn0; m1 = mn1;
        float sum0 = 0.f, sum1 = 0.f;
        #pragma unroll
        for (int nt = 0; nt < 16; nt++) {
            sfrag[nt][0] = __expf(sfrag[nt][0] - mn0);
            sfrag[nt][1] = __expf(sfrag[nt][1] - mn0);
            sfrag[nt][2] = __expf(sfrag[nt][2] - mn1);
            sfrag[nt][3] = __expf(sfrag[nt][3] - mn1);
            sum0 += sfrag[nt][0] + sfrag[nt][1];
            sum1 += sfrag[nt][2] + sfrag[nt][3];
        }
        sum0 += __shfl_xor_sync(0xffffffffu, sum0, 1);
        sum0 += __shfl_xor_sync(0xffffffffu, sum0, 2);
        sum1 += __shfl_xor_sync(0xffffffffu, sum1, 1);
        sum1 += __shfl_xor_sync(0xffffffffu, sum1, 2);
        l0 = l0*al0 + sum0;
        l1 = l1*al1 + sum1;

        #pragma unroll
        for (int dt = 0; dt < 8; dt++) {
            ofrag[dt][0] *= al0; ofrag[dt][1] *= al0;
            ofrag[dt][2] *= al1; ofrag[dt][3] *= al1;
        }

        // ---- O += P @ V : per k8-group, shfl-transpose P acc -> A-frag ----
        #pragma unroll
        for (int ks = 0; ks < 16; ks++) {
            uint32_t p0 = f2tf(sfrag[ks][0]);
            uint32_t p1 = f2tf(sfrag[ks][1]);
            uint32_t p2 = f2tf(sfrag[ks][2]);
            uint32_t p3 = f2tf(sfrag[ks][3]);
            uint32_t x0 = __shfl_sync(0xffffffffu, p0, src0);
            uint32_t y0 = __shfl_sync(0xffffffffu, p1, src0);
            uint32_t x2 = __shfl_sync(0xffffffffu, p0, src1);
            uint32_t y2 = __shfl_sync(0xffffffffu, p1, src1);
            uint32_t x1 = __shfl_sync(0xffffffffu, p2, src0);
            uint32_t y1 = __shfl_sync(0xffffffffu, p3, src0);
            uint32_t x3 = __shfl_sync(0xffffffffu, p2, src1);
            uint32_t y3 = __shfl_sync(0xffffffffu, p3, src1);
            uint32_t af[4];
            af[0] = oddl ? y0 : x0;
            af[1] = oddl ? y1 : x1;
            af[2] = oddl ? y2 : x2;
            af[3] = oddl ? y3 : x3;
            int vr0 = (ks*8 + tid4) * QS;
            int vr1 = (ks*8 + tid4 + 4) * QS;
            #pragma unroll
            for (int dt = 0; dt < 8; dt++) {
                uint32_t vb[2];
                vb[0] = Vc[vr0 + dt*8 + g];
                vb[1] = Vc[vr1 + dt*8 + g];
                mma_tf32(ofrag[dt], af, vb);
            }
        }
        __syncthreads();   // all warps done with Kc/Vc before they are refilled
    }

    // ---- normalize + store ----
    float inv0 = 1.0f / l0, inv1 = 1.0f / l1;
    int r0 = b*NQ + q0 + w*16 + g;
    #pragma unroll
    for (int dt = 0; dt < 8; dt++) {
        int col = dt*8 + 2*tid4;
        *(float2*)&AO[(size_t)r0*II + h*DD + col] =
            make_float2(ofrag[dt][0]*inv0, ofrag[dt][1]*inv0);
        *(float2*)&AO[(size_t)(r0 + 8)*II + h*DD + col] =
            make_float2(ofrag[dt][2]*inv1, ofrag[dt][3]*inv1);
    }
}

// ============================================================================
// launch
// ============================================================================
extern "C" void kernel_launch(void* const* d_in, const int* in_sizes, int n_in,
                              void* d_out, int out_size)
{
    const float* x   = (const float*)d_in[0];
    const float* ctx = (const float*)d_in[1];
    const float* Wq  = (const float*)d_in[2];
    const float* Wk  = (const float*)d_in[3];
    const float* Wv  = (const float*)d_in[4];
    const float* Wo  = (const float*)d_in[5];
    const float* bo  = (const float*)d_in[6];
    float* out = (float*)d_out;

    uint32_t *Qp, *Kp, *Vp;
    float *AOp;
    cudaGetSymbolAddress((void**)&Qp,  g_Q);
    cudaGetSymbolAddress((void**)&Kp,  g_K);
    cudaGetSymbolAddress((void**)&Vp,  g_V);
    cudaGetSymbolAddress((void**)&AOp, g_AO);

    dim3 blk(256);

    // fused Q/K/V projections (Q pre-scaled; Q,K pair-permuted)
    gemm_proj<<<dim3(II/128, (B_*NQ)/128, 3), blk>>>(x, ctx, Wq, Wk, Wv, Qp, Kp, Vp);

    // attention
    cudaFuncSetAttribute(attn_tf32, cudaFuncAttributeMaxDynamicSharedMemorySize, ATT_SMEM);
    attn_tf32<<<dim3(NQ/128, B_*HH), blk, ATT_SMEM>>>(Qp, Kp, Vp, AOp);

    // output projection + bias
    gemm_out<<<dim3(CQ/128, (B_*NQ)/128), blk>>>(AOp, Wo, bo, out);
}

// round 8
// speedup vs baseline: 3.6260x; 1.0726x over previous
#include <cuda_runtime.h>
#include <math.h>
#include <stdint.h>

// ---------------- problem constants ----------------
#define B_   2
#define NQ   2048
#define NKV  2048
#define CQ   1024
#define CK   768
#define HH   8
#define DD   64
#define II   (HH*DD)          // 512
#define SCALE 0.125f

// ---------------- scratch (all tf32 bit patterns) ----------------
// packed A operands: pcol pair-permuted within 8-col groups
__device__ uint32_t g_xp [B_*NQ *CQ];
__device__ uint32_t g_cp [B_*NKV*CK];
// packed B operands: (k,k+4) pair-rows: [(K/2)][N][2]
__device__ uint32_t g_Wqp[CQ*II];
__device__ uint32_t g_Wkp[CK*II];
__device__ uint32_t g_Wvp[CK*II];
__device__ uint32_t g_Wop[II*CQ];
// attention operands / results
__device__ uint32_t g_Q [B_*NQ *II];     // pair-permuted
__device__ uint32_t g_K [B_*NKV*II];     // pair-permuted
__device__ uint32_t g_V [B_*NKV*II];     // natural
__device__ uint32_t g_AO[B_*NQ *II];     // pair-permuted (A of out-proj)

// ---------------- helpers ----------------
__device__ __forceinline__ uint32_t f2tf(float f) {
    uint32_t u;
    asm("cvt.rna.tf32.f32 %0, %1;" : "=r"(u) : "f"(f));
    return u;
}
__device__ __forceinline__ void mma_hmma(float c[4], const uint32_t a[4], const uint32_t b[2]) {
    asm("mma.sync.aligned.m16n8k8.row.col.f32.tf32.tf32.f32 "
        "{%0,%1,%2,%3},{%4,%5,%6,%7},{%8,%9},{%0,%1,%2,%3};"
        : "+f"(c[0]), "+f"(c[1]), "+f"(c[2]), "+f"(c[3])
        : "r"(a[0]), "r"(a[1]), "r"(a[2]), "r"(a[3]), "r"(b[0]), "r"(b[1]));
}
__device__ __forceinline__ void cp16(void* sptr, const void* gptr) {
    uint32_t sa = (uint32_t)__cvta_generic_to_shared(sptr);
    asm volatile("cp.async.cg.shared.global [%0], [%1], 16;" :: "r"(sa), "l"(gptr));
}
#define CP_COMMIT() asm volatile("cp.async.commit_group;")

// pair-permute position within 8-group: [0,4,1,5,2,6,3,7]
__device__ __forceinline__ int pcol(int c) {
    return (c & ~7) | ((c & 3) << 1) | ((c & 7) >> 2);
}

// ============================================================================
// prep kernels
// ============================================================================
// f32 [M][K] -> tf32 pcol-packed (flat; K % 8 == 0)
__global__ void pack_a(const float4* __restrict__ in, uint32_t* __restrict__ out, int n4) {
    int i = blockIdx.x * blockDim.x + threadIdx.x;
    if (i >= n4) return;
    float4 v = in[i];
    int base = i * 4;
    int grp  = base & ~7;
    int off  = (base & 4) ? 1 : 0;
    out[grp + off + 0] = f2tf(v.x);
    out[grp + off + 2] = f2tf(v.y);
    out[grp + off + 4] = f2tf(v.z);
    out[grp + off + 6] = f2tf(v.w);
}

// W[K][N] f32 -> packed [(K/2)][N][2]: row kk=(s*8+pr) holds (W[k0], W[k0+4])
__global__ void pack_b(const float* __restrict__ in, uint32_t* __restrict__ out, int N) {
    int n  = blockIdx.x * 128 + threadIdx.x;
    int kk = blockIdx.y;
    int s  = kk >> 3;
    int pr = kk & 7;
    int k0 = s * 16 + ((pr >> 2) << 3) + (pr & 3);
    uint2 v = make_uint2(f2tf(in[(size_t)k0 * N + n]),
                         f2tf(in[(size_t)(k0 + 4) * N + n]));
    *(uint2*)&out[((size_t)kk * N + n) * 2] = v;
}

// ============================================================================
// TF32 GEMM, fully cp.async-fed: C[M,N] = A@B (+bias / tf32 out).
// CTA 128x128, BK=16, 8 warps (2x4), warp 64x32, 3-stage pipeline.
// A smem stride 24 (pairs packed), B smem 8 pair-rows x 264.
// mode: 0=Q (tf32, perm, *SCALE)  1=K (tf32, perm)  2=V (tf32)  3=f32+bias
// ============================================================================
#define AS 24
#define BSs 264
#define STG_A (128*AS)          // 3072 words
#define STG_B (8*BSs)           // 2112 words
#define STG_W (STG_A + STG_B)   // 5184 words
#define GEMM_SMEM (3*STG_W*4)   // 62208 B

__device__ __forceinline__ void gemm_body(const uint32_t* __restrict__ Ag,
                                          const uint32_t* __restrict__ Bp,
                                          const float* __restrict__ bias,
                                          void* __restrict__ Cv,
                                          int K, int Nn, int mode,
                                          uint32_t* sm)
{
    const int t    = threadIdx.x;
    const int lane = t & 31;
    const int w    = t >> 5;
    const int wrow = w >> 2;
    const int wcol = w & 3;
    const int g    = lane >> 2;
    const int tid4 = lane & 3;
    const int bm = blockIdx.y * 128;
    const int bn = blockIdx.x * 128;
    const int NCH = K >> 4;

    auto load = [&](int ch, int st) {
        uint32_t* ab = sm + st * STG_W;
        uint32_t* bb = ab + STG_A;
        const uint32_t* Asrc = Ag + (size_t)bm * K + ch * 16;
        const uint32_t* Bsrc = Bp + ((size_t)(ch * 8) * Nn + bn) * 2;
        #pragma unroll
        for (int j = 0; j < 2; j++) {
            int idx = t + j * 256;
            int r = idx >> 2, ck = idx & 3;
            cp16(&ab[r * AS + ck * 4], Asrc + (size_t)r * K + ck * 4);
        }
        #pragma unroll
        for (int j = 0; j < 2; j++) {
            int idx = t + j * 256;
            int pr = idx >> 6, nc = idx & 63;
            cp16(&bb[pr * BSs + nc * 4], Bsrc + ((size_t)pr * Nn + nc * 2) * 2);
        }
        CP_COMMIT();
    };

    float acc[4][4][4];
    #pragma unroll
    for (int mt = 0; mt < 4; mt++)
        #pragma unroll
        for (int nt = 0; nt < 4; nt++)
            #pragma unroll
            for (int e = 0; e < 4; e++) acc[mt][nt][e] = 0.f;

    load(0, 0);
    load(1, 1);

    for (int ch = 0; ch < NCH; ch++) {
        if (ch + 1 < NCH) asm volatile("cp.async.wait_group 1;" ::: "memory");
        else              asm volatile("cp.async.wait_group 0;" ::: "memory");
        __syncthreads();
        if (ch + 2 < NCH) load(ch + 2, (ch + 2) % 3);

        const uint32_t* Asc = sm + (ch % 3) * STG_W;
        const uint32_t* Bsc = Asc + STG_A;

        #pragma unroll
        for (int ks = 0; ks < 2; ks++) {
            uint32_t af[4][4], bf[4][2];
            #pragma unroll
            for (int mt = 0; mt < 4; mt++) {
                int r = wrow*64 + mt*16 + g;
                uint2 lo = *(const uint2*)&Asc[r*AS + ks*8 + 2*tid4];
                uint2 hi = *(const uint2*)&Asc[(r+8)*AS + ks*8 + 2*tid4];
                af[mt][0] = lo.x; af[mt][1] = hi.x; af[mt][2] = lo.y; af[mt][3] = hi.y;
            }
            #pragma unroll
            for (int nt = 0; nt < 4; nt++) {
                int cidx = wcol*32 + nt*8 + g;
                uint2 bb = *(const uint2*)&Bsc[(ks*4 + tid4)*BSs + 2*cidx];
                bf[nt][0] = bb.x; bf[nt][1] = bb.y;
            }
            #pragma unroll
            for (int mt = 0; mt < 4; mt++)
                #pragma unroll
                for (int nt = 0; nt < 4; nt++)
                    mma_hmma(acc[mt][nt], af[mt], bf[nt]);
        }
    }

    // epilogue
    #pragma unroll
    for (int mt = 0; mt < 4; mt++) {
        int row0 = bm + wrow*64 + mt*16 + g;
        #pragma unroll
        for (int nt = 0; nt < 4; nt++) {
            int col = bn + wcol*32 + nt*8 + 2*tid4;
            if (mode == 3) {
                float* C = (float*)Cv;
                float bx = bias[col], by = bias[col+1];
                *(float2*)&C[(size_t)row0 * Nn + col] =
                    make_float2(acc[mt][nt][0] + bx, acc[mt][nt][1] + by);
                *(float2*)&C[(size_t)(row0 + 8) * Nn + col] =
                    make_float2(acc[mt][nt][2] + bx, acc[mt][nt][3] + by);
            } else if (mode == 2) {
                uint32_t* C = (uint32_t*)Cv;
                *(uint2*)&C[(size_t)row0 * Nn + col] =
                    make_uint2(f2tf(acc[mt][nt][0]), f2tf(acc[mt][nt][1]));
                *(uint2*)&C[(size_t)(row0 + 8) * Nn + col] =
                    make_uint2(f2tf(acc[mt][nt][2]), f2tf(acc[mt][nt][3]));
            } else {
                const float sc = (mode == 0) ? SCALE : 1.0f;
                uint32_t* C = (uint32_t*)Cv;
                int c0 = pcol(col), c1 = pcol(col + 1);
                C[(size_t)row0 * Nn + c0]       = f2tf(acc[mt][nt][0] * sc);
                C[(size_t)row0 * Nn + c1]       = f2tf(acc[mt][nt][1] * sc);
                C[(size_t)(row0 + 8) * Nn + c0] = f2tf(acc[mt][nt][2] * sc);
                C[(size_t)(row0 + 8) * Nn + c1] = f2tf(acc[mt][nt][3] * sc);
            }
        }
    }
}

__global__ __launch_bounds__(256, 2) void gemm_proj() {
    extern __shared__ __align__(16) uint32_t sm[];
    const int z = blockIdx.z;
    const uint32_t* A  = (z == 0) ? g_xp  : g_cp;
    const uint32_t* Bp = (z == 0) ? g_Wqp : ((z == 1) ? g_Wkp : g_Wvp);
    uint32_t*       C  = (z == 0) ? g_Q   : ((z == 1) ? g_K   : g_V);
    const int       K  = (z == 0) ? CQ : CK;
    gemm_body(A, Bp, nullptr, C, K, II, z, sm);
}

__global__ __launch_bounds__(256, 2) void gemm_out(const float* __restrict__ bias,
                                                   float* __restrict__ out) {
    extern __shared__ __align__(16) uint32_t sm[];
    gemm_body(g_AO, g_Wop, bias, out, II, CQ, 3, sm);
}

// ============================================================================
// TF32 flash attention (R6-proven). AO written pcol-packed tf32.
// ============================================================================
#define QS 72
#define ATT_T_ELEMS (128*QS)
#define ATT_SMEM (5*ATT_T_ELEMS*4)           // 184320 B

__global__ __launch_bounds__(256, 1) void attn_tf32() {
    extern __shared__ __align__(16) uint32_t smu[];
    uint32_t* Qs  = smu;
    uint32_t* Kb0 = smu + ATT_T_ELEMS;
    uint32_t* Kb1 = smu + 2*ATT_T_ELEMS;
    uint32_t* Vb0 = smu + 3*ATT_T_ELEMS;
    uint32_t* Vb1 = smu + 4*ATT_T_ELEMS;

    const uint32_t* Qg = g_Q;
    const uint32_t* Kg = g_K;
    const uint32_t* Vg = g_V;

    const int t    = threadIdx.x;
    const int lane = t & 31;
    const int w    = t >> 5;
    const int g    = lane >> 2;
    const int tid4 = lane & 3;

    const int bh = blockIdx.y;
    const int b  = bh >> 3;
    const int h  = bh & 7;
    const int q0 = blockIdx.x * 128;

    #pragma unroll
    for (int j = 0; j < 8; j++) {
        int idx = t + j*256;
        int row = idx >> 4;
        int d   = (idx & 15) * 4;
        cp16(&Qs[row*QS + d], &Qg[(size_t)(b*NQ + q0 + row)*II + h*DD + d]);
    }
    #pragma unroll
    for (int j = 0; j < 8; j++) {
        int idx = t + j*256;
        int row = idx >> 4;
        int d   = (idx & 15) * 4;
        size_t grow = (size_t)(b*NKV + row)*II + h*DD + d;
        cp16(&Kb0[row*QS + d], &Kg[grow]);
        cp16(&Vb0[row*QS + d], &Vg[grow]);
    }
    CP_COMMIT();

    uint32_t qa[8][4];
    float ofrag[8][4];
    #pragma unroll
    for (int dt = 0; dt < 8; dt++)
        #pragma unroll
        for (int e = 0; e < 4; e++) ofrag[dt][e] = 0.f;
    float m0 = -1e30f, m1 = -1e30f, l0 = 0.f, l1 = 0.f;

    const int src0 = (lane & ~3) | (tid4 >> 1);
    const int src1 = src0 + 2;
    const bool oddl = tid4 & 1;

    for (int it = 0; it < NKV/128; it++) {
        const int cur = it & 1;
        uint32_t* Kc = cur ? Kb1 : Kb0;
        uint32_t* Vc = cur ? Vb1 : Vb0;

        if (it + 1 < NKV/128) {
            uint32_t* Kn = cur ? Kb0 : Kb1;
            uint32_t* Vn = cur ? Vb0 : Vb1;
            int kv0n = (it + 1) * 128;
            #pragma unroll
            for (int j = 0; j < 8; j++) {
                int idx = t + j*256;
                int row = idx >> 4;
                int d   = (idx & 15) * 4;
                size_t grow = (size_t)(b*NKV + kv0n + row)*II + h*DD + d;
                cp16(&Kn[row*QS + d], &Kg[grow]);
                cp16(&Vn[row*QS + d], &Vg[grow]);
            }
            CP_COMMIT();
            asm volatile("cp.async.wait_group 1;" ::: "memory");
        } else {
            asm volatile("cp.async.wait_group 0;" ::: "memory");
        }
        __syncthreads();

        if (it == 0) {
            int r0 = (w*16 + g) * QS;
            int r1 = (w*16 + g + 8) * QS;
            #pragma unroll
            for (int ks = 0; ks < 8; ks++) {
                uint2 lo = *(const uint2*)&Qs[r0 + ks*8 + 2*tid4];
                uint2 hi = *(const uint2*)&Qs[r1 + ks*8 + 2*tid4];
                qa[ks][0] = lo.x; qa[ks][1] = hi.x; qa[ks][2] = lo.y; qa[ks][3] = hi.y;
            }
        }

        float sfrag[16][4];
        #pragma unroll
        for (int nt = 0; nt < 16; nt++) {
            sfrag[nt][0]=0.f; sfrag[nt][1]=0.f; sfrag[nt][2]=0.f; sfrag[nt][3]=0.f;
            int krow = (nt*8 + g) * QS;
            #pragma unroll
            for (int ks = 0; ks < 8; ks++) {
                uint2 bb = *(const uint2*)&Kc[krow + ks*8 + 2*tid4];
                uint32_t bf[2] = {bb.x, bb.y};
                mma_hmma(sfrag[nt], qa[ks], bf);
            }
        }

        float tm0 = sfrag[0][0], tm1 = sfrag[0][2];
        #pragma unroll
        for (int nt = 0; nt < 16; nt++) {
            tm0 = fmaxf(tm0, fmaxf(sfrag[nt][0], sfrag[nt][1]));
            tm1 = fmaxf(tm1, fmaxf(sfrag[nt][2], sfrag[nt][3]));
        }
        tm0 = fmaxf(tm0, __shfl_xor_sync(0xffffffffu, tm0, 1));
        tm0 = fmaxf(tm0, __shfl_xor_sync(0xffffffffu, tm0, 2));
        tm1 = fmaxf(tm1, __shfl_xor_sync(0xffffffffu, tm1, 1));
        tm1 = fmaxf(tm1, __shfl_xor_sync(0xffffffffu, tm1, 2));
        float mn0 = fmaxf(m0, tm0), mn1 = fmaxf(m1, tm1);
        float al0 = __expf(m0 - mn0), al1 = __expf(m1 - mn1);
        m0 = mn0; m1 = mn1;
        float sum0 = 0.f, sum1 = 0.f;
        #pragma unroll
        for (int nt = 0; nt < 16; nt++) {
            sfrag[nt][0] = __expf(sfrag[nt][0] - mn0);
            sfrag[nt][1] = __expf(sfrag[nt][1] - mn0);
            sfrag[nt][2] = __expf(sfrag[nt][2] - mn1);
            sfrag[nt][3] = __expf(sfrag[nt][3] - mn1);
            sum0 += sfrag[nt][0] + sfrag[nt][1];
            sum1 += sfrag[nt][2] + sfrag[nt][3];
        }
        sum0 += __shfl_xor_sync(0xffffffffu, sum0, 1);
        sum0 += __shfl_xor_sync(0xffffffffu, sum0, 2);
        sum1 += __shfl_xor_sync(0xffffffffu, sum1, 1);
        sum1 += __shfl_xor_sync(0xffffffffu, sum1, 2);
        l0 = l0*al0 + sum0;
        l1 = l1*al1 + sum1;

        #pragma unroll
        for (int dt = 0; dt < 8; dt++) {
            ofrag[dt][0] *= al0; ofrag[dt][1] *= al0;
            ofrag[dt][2] *= al1; ofrag[dt][3] *= al1;
        }

        #pragma unroll
        for (int ks = 0; ks < 16; ks++) {
            uint32_t p0 = f2tf(sfrag[ks][0]);
            uint32_t p1 = f2tf(sfrag[ks][1]);
            uint32_t p2 = f2tf(sfrag[ks][2]);
            uint32_t p3 = f2tf(sfrag[ks][3]);
            uint32_t x0 = __shfl_sync(0xffffffffu, p0, src0);
            uint32_t y0 = __shfl_sync(0xffffffffu, p1, src0);
            uint32_t x2 = __shfl_sync(0xffffffffu, p0, src1);
            uint32_t y2 = __shfl_sync(0xffffffffu, p1, src1);
            uint32_t x1 = __shfl_sync(0xffffffffu, p2, src0);
            uint32_t y1 = __shfl_sync(0xffffffffu, p3, src0);
            uint32_t x3 = __shfl_sync(0xffffffffu, p2, src1);
            uint32_t y3 = __shfl_sync(0xffffffffu, p3, src1);
            uint32_t af[4];
            af[0] = oddl ? y0 : x0;
            af[1] = oddl ? y1 : x1;
            af[2] = oddl ? y2 : x2;
            af[3] = oddl ? y3 : x3;
            int vr0 = (ks*8 + tid4) * QS;
            int vr1 = (ks*8 + tid4 + 4) * QS;
            #pragma unroll
            for (int dt = 0; dt < 8; dt++) {
                uint32_t vb[2];
                vb[0] = Vc[vr0 + dt*8 + g];
                vb[1] = Vc[vr1 + dt*8 + g];
                mma_hmma(ofrag[dt], af, vb);
            }
        }
        __syncthreads();
    }

    // normalize + store pcol-packed tf32
    float inv0 = 1.0f / l0, inv1 = 1.0f / l1;
    int r0 = b*NQ + q0 + w*16 + g;
    uint32_t* AOu = g_AO;
    #pragma unroll
    for (int dt = 0; dt < 8; dt++) {
        int col = dt*8 + 2*tid4;
        int c0 = pcol(col), c1 = pcol(col + 1);
        size_t ro0 = (size_t)r0*II + h*DD;
        size_t ro1 = (size_t)(r0 + 8)*II + h*DD;
        AOu[ro0 + c0] = f2tf(ofrag[dt][0]*inv0);
        AOu[ro0 + c1] = f2tf(ofrag[dt][1]*inv0);
        AOu[ro1 + c0] = f2tf(ofrag[dt][2]*inv1);
        AOu[ro1 + c1] = f2tf(ofrag[dt][3]*inv1);
    }
}

// ============================================================================
// launch
// ============================================================================
extern "C" void kernel_launch(void* const* d_in, const int* in_sizes, int n_in,
                              void* d_out, int out_size)
{
    const float* x   = (const float*)d_in[0];
    const float* ctx = (const float*)d_in[1];
    const float* Wq  = (const float*)d_in[2];
    const float* Wk  = (const float*)d_in[3];
    const float* Wv  = (const float*)d_in[4];
    const float* Wo  = (const float*)d_in[5];
    const float* bo  = (const float*)d_in[6];
    float* out = (float*)d_out;

    uint32_t *xp, *cp, *Wqp, *Wkp, *Wvp, *Wop;
    cudaGetSymbolAddress((void**)&xp,  g_xp);
    cudaGetSymbolAddress((void**)&cp,  g_cp);
    cudaGetSymbolAddress((void**)&Wqp, g_Wqp);
    cudaGetSymbolAddress((void**)&Wkp, g_Wkp);
    cudaGetSymbolAddress((void**)&Wvp, g_Wvp);
    cudaGetSymbolAddress((void**)&Wop, g_Wop);

    // ---- prep: convert+pack activations and weights ----
    pack_a<<<(B_*NQ*CQ/4 + 255)/256, 256>>>((const float4*)x,   xp, B_*NQ*CQ/4);
    pack_a<<<(B_*NKV*CK/4 + 255)/256, 256>>>((const float4*)ctx, cp, B_*NKV*CK/4);
    pack_b<<<dim3(II/128, CQ/2), 128>>>(Wq, Wqp, II);
    pack_b<<<dim3(II/128, CK/2), 128>>>(Wk, Wkp, II);
    pack_b<<<dim3(II/128, CK/2), 128>>>(Wv, Wvp, II);
    pack_b<<<dim3(CQ/128, II/2), 128>>>(Wo, Wop, CQ);

    // ---- projections ----
    cudaFuncSetAttribute(gemm_proj, cudaFuncAttributeMaxDynamicSharedMemorySize, GEMM_SMEM);
    gemm_proj<<<dim3(II/128, (B_*NQ)/128, 3), 256, GEMM_SMEM>>>();

    // ---- attention ----
    cudaFuncSetAttribute(attn_tf32, cudaFuncAttributeMaxDynamicSharedMemorySize, ATT_SMEM);
    attn_tf32<<<dim3(NQ/128, B_*HH), 256, ATT_SMEM>>>();

    // ---- output projection + bias ----
    cudaFuncSetAttribute(gemm_out, cudaFuncAttributeMaxDynamicSharedMemorySize, GEMM_SMEM);
    gemm_out<<<dim3(CQ/128, (B_*NQ)/128), 256, GEMM_SMEM>>>(bo, out);
}